// round 4
// baseline (speedup 1.0000x reference)
#include <cuda_runtime.h>
#include <cstdint>

// Problem constants
#define SS   2048
#define DD   64
#define NBH  32            // B*H = 2*16
#define NMASK (1u << 27)   // total mask bits = B*H*S*S

// 2^27 mask bits packed -> 2^22 words (16 MB), static device scratch (no allocs allowed)
__device__ uint32_t g_mask[1u << 22];

// ---------------------------------------------------------------------------
// threefry2x32 with key (0, 42)  == jax.random.key(42) raw data [0, 42]
// ---------------------------------------------------------------------------
#define TF_K0 0u
#define TF_K1 42u
#define TF_K2 (0x1BD11BDAu ^ TF_K0 ^ TF_K1)

__device__ __forceinline__ void threefry(uint32_t c0, uint32_t c1,
                                         uint32_t& o0, uint32_t& o1) {
    uint32_t x0 = c0 + TF_K0;
    uint32_t x1 = c1 + TF_K1;
#define TFR(r) { x0 += x1; x1 = __funnelshift_l(x1, x1, (r)); x1 ^= x0; }
    TFR(13) TFR(15) TFR(26) TFR(6)
    x0 += TF_K1; x1 += TF_K2 + 1u;
    TFR(17) TFR(29) TFR(16) TFR(24)
    x0 += TF_K2; x1 += TF_K0 + 2u;
    TFR(13) TFR(15) TFR(26) TFR(6)
    x0 += TF_K0; x1 += TF_K1 + 3u;
    TFR(17) TFR(29) TFR(16) TFR(24)
    x0 += TF_K1; x1 += TF_K2 + 4u;
    TFR(13) TFR(15) TFR(26) TFR(6)
    x0 += TF_K2; x1 += TF_K0 + 5u;
#undef TFR
    o0 = x0; o1 = x1;
}

// jax_threefry_partitionable=True bitstream (default in modern JAX):
//   b1, b2 = threefry2x32(key, (uint32(i >> 32), uint32(i)))
//   bits32[i] = b1 ^ b2            # XOR fold for bit_width in [8,16,32]
// Here i < 2^27, so counter = (0, i).  keep(i) <=> MSB(b1 ^ b2) == 0.
__global__ void __launch_bounds__(256) mask_kernel() {
    const uint32_t lane   = threadIdx.x & 31u;
    const uint32_t gwarp  = (blockIdx.x * 256u + threadIdx.x) >> 5;
    const uint32_t nwarps = (gridDim.x * 256u) >> 5;
    for (uint32_t i0 = gwarp * 64u; i0 < NMASK; i0 += nwarps * 64u) {
        uint32_t o0a, o1a, o0b, o1b;
        threefry(0u, i0 + lane,       o0a, o1a);   // two independent calls ->
        threefry(0u, i0 + 32u + lane, o0b, o1b);   // 2-way ILP on the ALU chain
        uint32_t ba = __ballot_sync(0xffffffffu, (int)(o0a ^ o1a) >= 0);
        uint32_t bb = __ballot_sync(0xffffffffu, (int)(o0b ^ o1b) >= 0);
        if (lane == 0u) {
            g_mask[(i0 >> 5)]      = ba;
            g_mask[(i0 >> 5) + 1u] = bb;
        }
    }
}

// ---------------------------------------------------------------------------
// Flash attention, fp32. BR=BC=64, 256 threads, 4x4 register micro-tiles.
// sK uses an XOR swizzle keyed on (row>>2)&7 so the 16 column-lanes of the
// S-GEMM hit distinct banks for their LDS.128 row reads.
// ---------------------------------------------------------------------------
#define SKOFF(c, k4) (((c) << 7) + (((k4) ^ (((c) >> 2) & 7)) << 2))

__global__ void __launch_bounds__(256) attn_kernel(
    const float* __restrict__ q1, const float* __restrict__ q2,
    const float* __restrict__ k1, const float* __restrict__ k2,
    const float* __restrict__ v1, const float* __restrict__ v2,
    float* __restrict__ out)
{
    extern __shared__ float sm[];
    float* sQ = sm;                 // 64 x 128 (q1||q2, pre-scaled), plain stride
    float* sK = sQ + 64 * 128;      // 64 x 128 (k1||k2), XOR-swizzled
    float* sV = sK + 64 * 128;      // 64 x 68  (v1+v2)
    float* sP = sV + 64 * 68;       // 64 x 68  dropped exp-weights staging

    const int tid = threadIdx.x;
    const int tx  = tid & 15;       // column group (4 cols)
    const int ty  = tid >> 4;       // row group    (4 rows)
    const int bh  = blockIdx.y;     // b*16+h
    const int s0  = blockIdx.x << 6;
    const int base = bh * (SS * DD);

    // ---- load Q tile once, fold in scale = 1/sqrt(64) ----
    const float scale = 0.125f;
    for (int it = tid; it < 1024; it += 256) {
        int r = it >> 4, c = (it & 15) << 2;
        int g = base + (s0 + r) * DD + c;
        float4 a = *(const float4*)(q1 + g);
        float4 b = *(const float4*)(q2 + g);
        a.x *= scale; a.y *= scale; a.z *= scale; a.w *= scale;
        b.x *= scale; b.y *= scale; b.z *= scale; b.w *= scale;
        *(float4*)(sQ + r * 128 + c)      = a;
        *(float4*)(sQ + r * 128 + 64 + c) = b;
    }

    float m0[4], l0[4], accO[4][4];
#pragma unroll
    for (int j = 0; j < 4; j++) {
        m0[j] = -3.0e38f; l0[j] = 0.0f;
#pragma unroll
        for (int i = 0; i < 4; i++) accO[j][i] = 0.0f;
    }

    for (int t0 = 0; t0 < SS; t0 += 64) {
        __syncthreads();   // previous iteration's sP/sV reads done

        // ---- load K (swizzled) and V=v1+v2 tiles ----
        for (int it = tid; it < 1024; it += 256) {
            int r = it >> 4; int c4 = it & 15; int c = c4 << 2;
            int g = base + (t0 + r) * DD + c;
            float4 ka = *(const float4*)(k1 + g);
            float4 kb = *(const float4*)(k2 + g);
            *(float4*)(sK + SKOFF(r, c4))      = ka;
            *(float4*)(sK + SKOFF(r, c4 + 16)) = kb;
            float4 va = *(const float4*)(v1 + g);
            float4 vb = *(const float4*)(v2 + g);
            va.x += vb.x; va.y += vb.y; va.z += vb.z; va.w += vb.w;
            *(float4*)(sV + r * 68 + c) = va;
        }
        __syncthreads();

        // ---- S tile: (64x64) = Q(64x128) . K(64x128)^T ----
        float acc[4][4];
#pragma unroll
        for (int j = 0; j < 4; j++)
#pragma unroll
            for (int i = 0; i < 4; i++) acc[j][i] = 0.0f;

#pragma unroll 8
        for (int k4 = 0; k4 < 32; k4++) {
            const int kf = k4 << 2;
            float4 a0 = *(const float4*)(sQ + (ty * 4 + 0) * 128 + kf);
            float4 a1 = *(const float4*)(sQ + (ty * 4 + 1) * 128 + kf);
            float4 a2 = *(const float4*)(sQ + (ty * 4 + 2) * 128 + kf);
            float4 a3 = *(const float4*)(sQ + (ty * 4 + 3) * 128 + kf);
            float4 b0 = *(const float4*)(sK + SKOFF(tx * 4 + 0, k4));
            float4 b1 = *(const float4*)(sK + SKOFF(tx * 4 + 1, k4));
            float4 b2 = *(const float4*)(sK + SKOFF(tx * 4 + 2, k4));
            float4 b3 = *(const float4*)(sK + SKOFF(tx * 4 + 3, k4));
#define DOT4(j, i, A, Bv) acc[j][i] += A.x*Bv.x + A.y*Bv.y + A.z*Bv.z + A.w*Bv.w;
            DOT4(0,0,a0,b0) DOT4(0,1,a0,b1) DOT4(0,2,a0,b2) DOT4(0,3,a0,b3)
            DOT4(1,0,a1,b0) DOT4(1,1,a1,b1) DOT4(1,2,a1,b2) DOT4(1,3,a1,b3)
            DOT4(2,0,a2,b0) DOT4(2,1,a2,b1) DOT4(2,2,a2,b2) DOT4(2,3,a2,b3)
            DOT4(3,0,a3,b0) DOT4(3,1,a3,b1) DOT4(3,2,a3,b2) DOT4(3,3,a3,b3)
#undef DOT4
        }

        // ---- online softmax + dropout mask ----
        // flat mask idx = bh*2^22 + s*2048 + t ; word = idx>>5 ; bit = t&31
        const uint32_t mrow = ((uint32_t)bh << 17) + ((uint32_t)t0 >> 5) + (uint32_t)(tx >> 3);
        const int shbase = (tx & 7) << 2;
#pragma unroll
        for (int j = 0; j < 4; j++) {
            const int s = s0 + ty * 4 + j;
            float mx = fmaxf(fmaxf(acc[j][0], acc[j][1]), fmaxf(acc[j][2], acc[j][3]));
#pragma unroll
            for (int o = 8; o; o >>= 1)
                mx = fmaxf(mx, __shfl_xor_sync(0xffffffffu, mx, o, 16));
            const float newm = fmaxf(m0[j], mx);
            const float f = __expf(m0[j] - newm);
            float p[4];
            float rs = 0.0f;
#pragma unroll
            for (int i = 0; i < 4; i++) { p[i] = __expf(acc[j][i] - newm); rs += p[i]; }
#pragma unroll
            for (int o = 8; o; o >>= 1)
                rs += __shfl_xor_sync(0xffffffffu, rs, o, 16);
            l0[j] = l0[j] * f + rs;   // denominator WITHOUT dropout
            m0[j] = newm;
#pragma unroll
            for (int i = 0; i < 4; i++) accO[j][i] *= f;

            const uint32_t w = g_mask[mrow + ((uint32_t)s << 6)];
            float* sPr = sP + (ty * 4 + j) * 68 + (tx << 2);
#pragma unroll
            for (int i = 0; i < 4; i++)
                sPr[i] = ((w >> (shbase + i)) & 1u) ? p[i] : 0.0f;
        }
        __syncthreads();

        // ---- O += P(64x64) . V(64x64) ----
#pragma unroll 8
        for (int t = 0; t < 64; t++) {
            float a0 = sP[(ty * 4 + 0) * 68 + t];
            float a1 = sP[(ty * 4 + 1) * 68 + t];
            float a2 = sP[(ty * 4 + 2) * 68 + t];
            float a3 = sP[(ty * 4 + 3) * 68 + t];
            float4 bv = *(const float4*)(sV + t * 68 + (tx << 2));
            accO[0][0] += a0 * bv.x; accO[0][1] += a0 * bv.y; accO[0][2] += a0 * bv.z; accO[0][3] += a0 * bv.w;
            accO[1][0] += a1 * bv.x; accO[1][1] += a1 * bv.y; accO[1][2] += a1 * bv.z; accO[1][3] += a1 * bv.w;
            accO[2][0] += a2 * bv.x; accO[2][1] += a2 * bv.y; accO[2][2] += a2 * bv.z; accO[2][3] += a2 * bv.w;
            accO[3][0] += a3 * bv.x; accO[3][1] += a3 * bv.y; accO[3][2] += a3 * bv.z; accO[3][3] += a3 * bv.w;
        }
    }

    // ---- epilogue: x (1/(1-p)) / l ----
#pragma unroll
    for (int j = 0; j < 4; j++) {
        const float inv = 2.0f / l0[j];
        float4 o;
        o.x = accO[j][0] * inv; o.y = accO[j][1] * inv;
        o.z = accO[j][2] * inv; o.w = accO[j][3] * inv;
        *(float4*)(out + base + (s0 + ty * 4 + j) * DD + (tx << 2)) = o;
    }
}

// ---------------------------------------------------------------------------
extern "C" void kernel_launch(void* const* d_in, const int* in_sizes, int n_in,
                              void* d_out, int out_size) {
    (void)in_sizes; (void)n_in; (void)out_size;
    const float* q1 = (const float*)d_in[0];
    const float* q2 = (const float*)d_in[1];
    const float* k1 = (const float*)d_in[2];
    const float* k2 = (const float*)d_in[3];
    const float* v1 = (const float*)d_in[4];
    const float* v2 = (const float*)d_in[5];
    float* out = (float*)d_out;

    // 1) deterministic dropout bitmask (partitionable threefry, key (0,42), XOR fold)
    mask_kernel<<<2048, 256>>>();

    // 2) fused flash attention reading the bitmask
    const int smem_bytes = (64 * 128 * 2 + 64 * 68 * 2) * (int)sizeof(float); // 100352
    cudaFuncSetAttribute(attn_kernel,
                         cudaFuncAttributeMaxDynamicSharedMemorySize, smem_bytes);
    attn_kernel<<<dim3(SS / 64, NBH), 256, smem_bytes>>>(q1, q2, k1, k2, v1, v2, out);
}

// round 5
// speedup vs baseline: 1.4258x; 1.4258x over previous
#include <cuda_runtime.h>
#include <cuda_bf16.h>
#include <cstdint>

// Problem constants
#define SS   2048
#define DD   64
#define NBH  32            // B*H = 2*16
#define NMASK (1u << 27)   // total mask bits = B*H*S*S

// Static device scratch (no allocs allowed)
__device__ uint32_t g_mask[1u << 22];                 // 16 MB packed dropout bits
__device__ __nv_bfloat16 gQh[NBH * SS * 128];         // 16 MB  scaled Q concat, hi
__device__ __nv_bfloat16 gQl[NBH * SS * 128];         // 16 MB  lo
__device__ __nv_bfloat16 gKh[NBH * SS * 128];         // 16 MB  K concat, hi
__device__ __nv_bfloat16 gKl[NBH * SS * 128];         // 16 MB  lo
__device__ float         gVs[NBH * SS * 64];          // 16 MB  v1+v2

// ---------------------------------------------------------------------------
// threefry2x32, key (0, 42); partitionable bitstream: bits = out0 ^ out1
// ---------------------------------------------------------------------------
#define TF_K0 0u
#define TF_K1 42u
#define TF_K2 (0x1BD11BDAu ^ TF_K0 ^ TF_K1)

__device__ __forceinline__ void threefry(uint32_t c0, uint32_t c1,
                                         uint32_t& o0, uint32_t& o1) {
    uint32_t x0 = c0 + TF_K0;
    uint32_t x1 = c1 + TF_K1;
#define TFR(r) { x0 += x1; x1 = __funnelshift_l(x1, x1, (r)); x1 ^= x0; }
    TFR(13) TFR(15) TFR(26) TFR(6)
    x0 += TF_K1; x1 += TF_K2 + 1u;
    TFR(17) TFR(29) TFR(16) TFR(24)
    x0 += TF_K2; x1 += TF_K0 + 2u;
    TFR(13) TFR(15) TFR(26) TFR(6)
    x0 += TF_K0; x1 += TF_K1 + 3u;
    TFR(17) TFR(29) TFR(16) TFR(24)
    x0 += TF_K1; x1 += TF_K2 + 4u;
    TFR(13) TFR(15) TFR(26) TFR(6)
    x0 += TF_K2; x1 += TF_K0 + 5u;
#undef TFR
    o0 = x0; o1 = x1;
}

__global__ void __launch_bounds__(256) mask_kernel() {
    const uint32_t lane   = threadIdx.x & 31u;
    const uint32_t gwarp  = (blockIdx.x * 256u + threadIdx.x) >> 5;
    const uint32_t nwarps = (gridDim.x * 256u) >> 5;
    for (uint32_t i0 = gwarp * 64u; i0 < NMASK; i0 += nwarps * 64u) {
        uint32_t o0a, o1a, o0b, o1b;
        threefry(0u, i0 + lane,       o0a, o1a);
        threefry(0u, i0 + 32u + lane, o0b, o1b);
        uint32_t ba = __ballot_sync(0xffffffffu, (int)(o0a ^ o1a) >= 0);
        uint32_t bb = __ballot_sync(0xffffffffu, (int)(o0b ^ o1b) >= 0);
        if (lane == 0u) {
            g_mask[(i0 >> 5)]      = ba;
            g_mask[(i0 >> 5) + 1u] = bb;
        }
    }
}

// ---------------------------------------------------------------------------
// Prep: split scaled Q (q1||q2) and K (k1||k2) into bf16 hi/lo; V = v1+v2.
// ---------------------------------------------------------------------------
__device__ __forceinline__ void split4(float4 v, uint2& hi, uint2& lo) {
    __nv_bfloat16 h0 = __float2bfloat16_rn(v.x);
    __nv_bfloat16 h1 = __float2bfloat16_rn(v.y);
    __nv_bfloat16 h2 = __float2bfloat16_rn(v.z);
    __nv_bfloat16 h3 = __float2bfloat16_rn(v.w);
    __nv_bfloat16 l0 = __float2bfloat16_rn(v.x - __bfloat162float(h0));
    __nv_bfloat16 l1 = __float2bfloat16_rn(v.y - __bfloat162float(h1));
    __nv_bfloat16 l2 = __float2bfloat16_rn(v.z - __bfloat162float(h2));
    __nv_bfloat16 l3 = __float2bfloat16_rn(v.w - __bfloat162float(h3));
    hi.x = (uint32_t)*(uint16_t*)&h0 | ((uint32_t)*(uint16_t*)&h1 << 16);
    hi.y = (uint32_t)*(uint16_t*)&h2 | ((uint32_t)*(uint16_t*)&h3 << 16);
    lo.x = (uint32_t)*(uint16_t*)&l0 | ((uint32_t)*(uint16_t*)&l1 << 16);
    lo.y = (uint32_t)*(uint16_t*)&l2 | ((uint32_t)*(uint16_t*)&l3 << 16);
}

__global__ void __launch_bounds__(256) prep_kernel(
    const float* __restrict__ q1, const float* __restrict__ q2,
    const float* __restrict__ k1, const float* __restrict__ k2,
    const float* __restrict__ v1, const float* __restrict__ v2)
{
    const int idx4 = blockIdx.x * 256 + threadIdx.x;   // grid covers N/4 exactly
    const int row  = idx4 >> 4;        // bh*2048 + s
    const int d4   = idx4 & 15;        // float4 index within D=64
    const float4 a1 = ((const float4*)q1)[idx4];
    const float4 a2 = ((const float4*)q2)[idx4];
    const float4 b1 = ((const float4*)k1)[idx4];
    const float4 b2 = ((const float4*)k2)[idx4];
    const float4 c1 = ((const float4*)v1)[idx4];
    const float4 c2 = ((const float4*)v2)[idx4];
    const float s = 0.125f;
    float4 sa1 = make_float4(a1.x*s, a1.y*s, a1.z*s, a1.w*s);
    float4 sa2 = make_float4(a2.x*s, a2.y*s, a2.z*s, a2.w*s);
    uint2 hi, lo;
    const int qb = row * 128 + d4 * 4;
    split4(sa1, hi, lo);
    *(uint2*)(gQh + qb) = hi;      *(uint2*)(gQl + qb) = lo;
    split4(sa2, hi, lo);
    *(uint2*)(gQh + qb + 64) = hi; *(uint2*)(gQl + qb + 64) = lo;
    split4(b1, hi, lo);
    *(uint2*)(gKh + qb) = hi;      *(uint2*)(gKl + qb) = lo;
    split4(b2, hi, lo);
    *(uint2*)(gKh + qb + 64) = hi; *(uint2*)(gKl + qb + 64) = lo;
    ((float4*)gVs)[idx4] = make_float4(c1.x+c2.x, c1.y+c2.y, c1.z+c2.z, c1.w+c2.w);
}

// ---------------------------------------------------------------------------
// mma.sync helpers
// ---------------------------------------------------------------------------
__device__ __forceinline__ void ldsm_x4(uint32_t& r0, uint32_t& r1,
                                        uint32_t& r2, uint32_t& r3, uint32_t addr) {
    asm volatile("ldmatrix.sync.aligned.m8n8.x4.shared.b16 {%0,%1,%2,%3}, [%4];"
                 : "=r"(r0), "=r"(r1), "=r"(r2), "=r"(r3) : "r"(addr));
}
__device__ __forceinline__ void mma_bf16(float* c, const uint32_t* a,
                                         uint32_t b0, uint32_t b1) {
    asm volatile("mma.sync.aligned.m16n8k16.row.col.f32.bf16.bf16.f32 "
                 "{%0,%1,%2,%3}, {%4,%5,%6,%7}, {%8,%9}, {%0,%1,%2,%3};"
                 : "+f"(c[0]), "+f"(c[1]), "+f"(c[2]), "+f"(c[3])
                 : "r"(a[0]), "r"(a[1]), "r"(a[2]), "r"(a[3]), "r"(b0), "r"(b1));
}

// bf16 tile smem swizzle: row stride 128 bf16 (=16 chunks of 8 bf16);
// chunk' = chunk ^ (row & 7). Returns offset in bf16 units.
__device__ __forceinline__ int swb(int r, int ch) {
    return r * 128 + ((ch ^ (r & 7)) << 3);
}

// ---------------------------------------------------------------------------
// Flash attention: QK^T on tensor cores (bf16 hi/lo split, 3 MMAs), fp32 PV.
// BR=BC=64, 256 threads (8 warps: 4 row-blocks x 2 col-blocks of 16x32).
// ---------------------------------------------------------------------------
__global__ void __launch_bounds__(256, 2) attn_kernel(float* __restrict__ out)
{
    extern __shared__ char smem[];
    __nv_bfloat16* sQh = (__nv_bfloat16*)(smem);            // 64x128 bf16 16KB
    __nv_bfloat16* sQl = (__nv_bfloat16*)(smem + 16384);
    __nv_bfloat16* sKh = (__nv_bfloat16*)(smem + 32768);
    __nv_bfloat16* sKl = (__nv_bfloat16*)(smem + 49152);
    float* sV  = (float*)(smem + 65536);                    // 64x68 f32
    float* sSP = (float*)(smem + 65536 + 17408);            // 64x68 f32 (S then P, in-place)

    const int tid = threadIdx.x;
    const int lane = tid & 31;
    const int w    = tid >> 5;
    const int w_r  = w & 3;          // 16-row block
    const int w_c  = w >> 2;         // 32-col block
    const int tx  = tid & 15;        // softmax/PV column group (4 cols)
    const int ty  = tid >> 4;        // softmax/PV row group    (4 rows)
    const int bh  = blockIdx.y;
    const int s0  = blockIdx.x << 6;
    const int base = bh * (SS * DD);
    const size_t rowbase = (size_t)bh * SS * 128;

    // ---- load Q tile (bf16 hi/lo, swizzled) once ----
    {
        const uint4* gh = (const uint4*)(gQh + rowbase + (size_t)s0 * 128);
        const uint4* gl = (const uint4*)(gQl + rowbase + (size_t)s0 * 128);
        for (int it = tid; it < 1024; it += 256) {
            int r = it >> 4, ch = it & 15;
            int off = swb(r, ch);
            *(uint4*)(sQh + off) = gh[r * 16 + ch];
            *(uint4*)(sQl + off) = gl[r * 16 + ch];
        }
    }

    float m0[4], l0[4], accO[4][4];
#pragma unroll
    for (int j = 0; j < 4; j++) {
        m0[j] = -3.0e38f; l0[j] = 0.0f;
#pragma unroll
        for (int i = 0; i < 4; i++) accO[j][i] = 0.0f;
    }

    // ldmatrix smem addresses (lane-dependent row/chunk pieces)
    const uint32_t sQh_a = (uint32_t)__cvta_generic_to_shared(sQh);
    const uint32_t sQl_a = (uint32_t)__cvta_generic_to_shared(sQl);
    const uint32_t sKh_a = (uint32_t)__cvta_generic_to_shared(sKh);
    const uint32_t sKl_a = (uint32_t)__cvta_generic_to_shared(sKl);
    const int arow  = 16 * w_r + (lane & 15);
    const int g     = lane >> 3;
    const int brow0 = 32 * w_c + 8 * (g >> 1) + (lane & 7);   // nt pair 0 (nt0/nt1)
    const int brow1 = brow0 + 16;                              // nt pair 1 (nt2/nt3)
    const int bpar  = g & 1;

    for (int t0 = 0; t0 < SS; t0 += 64) {
        __syncthreads();   // prev iteration's sSP/sV reads done

        // ---- load K (bf16 hi/lo, swizzled) and V tiles ----
        {
            const uint4* gh = (const uint4*)(gKh + rowbase + (size_t)t0 * 128);
            const uint4* gl = (const uint4*)(gKl + rowbase + (size_t)t0 * 128);
            const float4* gv = (const float4*)(gVs + (size_t)bh * SS * 64 + (size_t)t0 * 64);
            for (int it = tid; it < 1024; it += 256) {
                int r = it >> 4, ch = it & 15;
                int off = swb(r, ch);
                *(uint4*)(sKh + off) = gh[r * 16 + ch];
                *(uint4*)(sKl + off) = gl[r * 16 + ch];
                *(float4*)(sV + r * 68 + (ch << 2)) = gv[r * 16 + ch];
            }
        }
        __syncthreads();

        // ---- S tile (64x64) via tensor cores: Qh*Kh + Qh*Kl + Ql*Kh ----
        float c0[4], c1[4], c2[4], c3[4];
#pragma unroll
        for (int i = 0; i < 4; i++) { c0[i] = 0.f; c1[i] = 0.f; c2[i] = 0.f; c3[i] = 0.f; }

#pragma unroll
        for (int kb = 0; kb < 8; kb++) {
            const int ach = 2 * kb + (lane >> 4);
            const uint32_t aoff = (uint32_t)(swb(arow, ach) * 2);
            uint32_t qh[4], ql[4];
            ldsm_x4(qh[0], qh[1], qh[2], qh[3], sQh_a + aoff);
            ldsm_x4(ql[0], ql[1], ql[2], ql[3], sQl_a + aoff);

            const int bch = 2 * kb + bpar;
            const uint32_t b0off = (uint32_t)(swb(brow0, bch) * 2);
            const uint32_t b1off = (uint32_t)(swb(brow1, bch) * 2);
            uint32_t kh0[4], kl0[4], kh1[4], kl1[4];
            ldsm_x4(kh0[0], kh0[1], kh0[2], kh0[3], sKh_a + b0off);
            ldsm_x4(kl0[0], kl0[1], kl0[2], kl0[3], sKl_a + b0off);
            ldsm_x4(kh1[0], kh1[1], kh1[2], kh1[3], sKh_a + b1off);
            ldsm_x4(kl1[0], kl1[1], kl1[2], kl1[3], sKl_a + b1off);

            mma_bf16(c0, qh, kh0[0], kh0[1]);
            mma_bf16(c0, qh, kl0[0], kl0[1]);
            mma_bf16(c0, ql, kh0[0], kh0[1]);
            mma_bf16(c1, qh, kh0[2], kh0[3]);
            mma_bf16(c1, qh, kl0[2], kl0[3]);
            mma_bf16(c1, ql, kh0[2], kh0[3]);
            mma_bf16(c2, qh, kh1[0], kh1[1]);
            mma_bf16(c2, qh, kl1[0], kl1[1]);
            mma_bf16(c2, ql, kh1[0], kh1[1]);
            mma_bf16(c3, qh, kh1[2], kh1[3]);
            mma_bf16(c3, qh, kl1[2], kl1[3]);
            mma_bf16(c3, ql, kh1[2], kh1[3]);
        }

        // ---- scatter score fragments to sSP ----
        {
            const int srow = 16 * w_r + (lane >> 2);
            const int scol = 32 * w_c + 2 * (lane & 3);
            *(float2*)(sSP + srow * 68 + scol)            = make_float2(c0[0], c0[1]);
            *(float2*)(sSP + (srow + 8) * 68 + scol)      = make_float2(c0[2], c0[3]);
            *(float2*)(sSP + srow * 68 + scol + 8)        = make_float2(c1[0], c1[1]);
            *(float2*)(sSP + (srow + 8) * 68 + scol + 8)  = make_float2(c1[2], c1[3]);
            *(float2*)(sSP + srow * 68 + scol + 16)       = make_float2(c2[0], c2[1]);
            *(float2*)(sSP + (srow + 8) * 68 + scol + 16) = make_float2(c2[2], c2[3]);
            *(float2*)(sSP + srow * 68 + scol + 24)       = make_float2(c3[0], c3[1]);
            *(float2*)(sSP + (srow + 8) * 68 + scol + 24) = make_float2(c3[2], c3[3]);
        }
        __syncthreads();

        // ---- online softmax + dropout mask (reads sSP 4x4, writes P in place) ----
        const uint32_t mrow = ((uint32_t)bh << 17) + ((uint32_t)t0 >> 5) + (uint32_t)(tx >> 3);
        const int shbase = (tx & 7) << 2;
#pragma unroll
        for (int j = 0; j < 4; j++) {
            const int s = s0 + ty * 4 + j;
            float4 av = *(const float4*)(sSP + (ty * 4 + j) * 68 + (tx << 2));
            float acc[4] = {av.x, av.y, av.z, av.w};
            float mx = fmaxf(fmaxf(acc[0], acc[1]), fmaxf(acc[2], acc[3]));
#pragma unroll
            for (int o = 8; o; o >>= 1)
                mx = fmaxf(mx, __shfl_xor_sync(0xffffffffu, mx, o, 16));
            const float newm = fmaxf(m0[j], mx);
            const float f = __expf(m0[j] - newm);
            float p[4];
            float rs = 0.0f;
#pragma unroll
            for (int i = 0; i < 4; i++) { p[i] = __expf(acc[i] - newm); rs += p[i]; }
#pragma unroll
            for (int o = 8; o; o >>= 1)
                rs += __shfl_xor_sync(0xffffffffu, rs, o, 16);
            l0[j] = l0[j] * f + rs;   // denominator WITHOUT dropout
            m0[j] = newm;
#pragma unroll
            for (int i = 0; i < 4; i++) accO[j][i] *= f;

            const uint32_t wmask = g_mask[mrow + ((uint32_t)s << 6)];
            float* sPr = sSP + (ty * 4 + j) * 68 + (tx << 2);
#pragma unroll
            for (int i = 0; i < 4; i++)
                sPr[i] = ((wmask >> (shbase + i)) & 1u) ? p[i] : 0.0f;
        }
        __syncthreads();

        // ---- O += P(64x64) . V(64x64), fp32 FFMA ----
#pragma unroll 8
        for (int t = 0; t < 64; t++) {
            float a0 = sSP[(ty * 4 + 0) * 68 + t];
            float a1 = sSP[(ty * 4 + 1) * 68 + t];
            float a2 = sSP[(ty * 4 + 2) * 68 + t];
            float a3 = sSP[(ty * 4 + 3) * 68 + t];
            float4 bv = *(const float4*)(sV + t * 68 + (tx << 2));
            accO[0][0] += a0 * bv.x; accO[0][1] += a0 * bv.y; accO[0][2] += a0 * bv.z; accO[0][3] += a0 * bv.w;
            accO[1][0] += a1 * bv.x; accO[1][1] += a1 * bv.y; accO[1][2] += a1 * bv.z; accO[1][3] += a1 * bv.w;
            accO[2][0] += a2 * bv.x; accO[2][1] += a2 * bv.y; accO[2][2] += a2 * bv.z; accO[2][3] += a2 * bv.w;
            accO[3][0] += a3 * bv.x; accO[3][1] += a3 * bv.y; accO[3][2] += a3 * bv.z; accO[3][3] += a3 * bv.w;
        }
    }

    // ---- epilogue: x (1/(1-p)) / l ----
#pragma unroll
    for (int j = 0; j < 4; j++) {
        const float inv = 2.0f / l0[j];
        float4 o;
        o.x = accO[j][0] * inv; o.y = accO[j][1] * inv;
        o.z = accO[j][2] * inv; o.w = accO[j][3] * inv;
        *(float4*)(out + base + (s0 + ty * 4 + j) * DD + (tx << 2)) = o;
    }
}

// ---------------------------------------------------------------------------
extern "C" void kernel_launch(void* const* d_in, const int* in_sizes, int n_in,
                              void* d_out, int out_size) {
    (void)in_sizes; (void)n_in; (void)out_size;
    const float* q1 = (const float*)d_in[0];
    const float* q2 = (const float*)d_in[1];
    const float* k1 = (const float*)d_in[2];
    const float* k2 = (const float*)d_in[3];
    const float* v1 = (const float*)d_in[4];
    const float* v2 = (const float*)d_in[5];
    float* out = (float*)d_out;

    mask_kernel<<<2048, 256>>>();
    prep_kernel<<<(NBH * SS * DD / 4) / 256, 256>>>(q1, q2, k1, k2, v1, v2);

    const int smem_bytes = 65536 + 2 * 17408;  // 100352
    cudaFuncSetAttribute(attn_kernel,
                         cudaFuncAttributeMaxDynamicSharedMemorySize, smem_bytes);
    attn_kernel<<<dim3(SS / 64, NBH), 256, smem_bytes>>>(out);
}

// round 6
// speedup vs baseline: 1.7582x; 1.2331x over previous
#include <cuda_runtime.h>
#include <cuda_bf16.h>
#include <cstdint>

// Problem constants
#define SS   2048
#define DD   64
#define NBH  32            // B*H = 2*16
#define NMASK (1u << 27)   // total mask bits = B*H*S*S

// Static device scratch (no allocs allowed)
__device__ uint32_t g_mask[1u << 22];                 // 16 MB packed dropout bits
__device__ uint32_t g_one = 1;                        // opaque 1 (forces IMAD pipe)
__device__ __nv_bfloat16 gQh[NBH * SS * 128];         // scaled Q concat, hi
__device__ __nv_bfloat16 gQl[NBH * SS * 128];         // lo
__device__ __nv_bfloat16 gKh[NBH * SS * 128];         // K concat, hi
__device__ __nv_bfloat16 gKl[NBH * SS * 128];         // lo
__device__ __nv_bfloat16 gVh[NBH * SS * 64];          // v1+v2, hi
__device__ __nv_bfloat16 gVl[NBH * SS * 64];          // lo

// ---------------------------------------------------------------------------
// threefry2x32, key (0, 42); partitionable bitstream: bits = out0 ^ out1
// Adds routed through IMAD (x + y*one) to balance ALU/FMA pipes.
// ---------------------------------------------------------------------------
#define TF_K0 0u
#define TF_K1 42u
#define TF_K2 (0x1BD11BDAu ^ TF_K0 ^ TF_K1)

__device__ __forceinline__ uint32_t addi(uint32_t a, uint32_t b, uint32_t one) {
    uint32_t r;
    asm("mad.lo.u32 %0, %1, %2, %3;" : "=r"(r) : "r"(b), "r"(one), "r"(a));
    return r;
}

__device__ __forceinline__ void threefry(uint32_t c0, uint32_t c1,
                                         uint32_t& o0, uint32_t& o1, uint32_t one) {
    uint32_t x0 = c0 + TF_K0;
    uint32_t x1 = c1 + TF_K1;
#define TFR(r) { x0 = addi(x0, x1, one); x1 = __funnelshift_l(x1, x1, (r)); x1 ^= x0; }
    TFR(13) TFR(15) TFR(26) TFR(6)
    x0 = addi(x0, TF_K1, one); x1 = addi(x1, TF_K2 + 1u, one);
    TFR(17) TFR(29) TFR(16) TFR(24)
    x0 = addi(x0, TF_K2, one); x1 = addi(x1, TF_K0 + 2u, one);
    TFR(13) TFR(15) TFR(26) TFR(6)
    x0 = addi(x0, TF_K0, one); x1 = addi(x1, TF_K1 + 3u, one);
    TFR(17) TFR(29) TFR(16) TFR(24)
    x0 = addi(x0, TF_K1, one); x1 = addi(x1, TF_K2 + 4u, one);
    TFR(13) TFR(15) TFR(26) TFR(6)
    x0 = addi(x0, TF_K2, one); x1 = addi(x1, TF_K0 + 5u, one);
#undef TFR
    o0 = x0; o1 = x1;
}

__global__ void __launch_bounds__(256) mask_kernel() {
    const uint32_t one = *((volatile const uint32_t*)&g_one);
    const uint32_t lane   = threadIdx.x & 31u;
    const uint32_t gwarp  = (blockIdx.x * 256u + threadIdx.x) >> 5;
    const uint32_t nwarps = (gridDim.x * 256u) >> 5;
    for (uint32_t i0 = gwarp * 64u; i0 < NMASK; i0 += nwarps * 64u) {
        uint32_t o0a, o1a, o0b, o1b;
        threefry(0u, i0 + lane,       o0a, o1a, one);
        threefry(0u, i0 + 32u + lane, o0b, o1b, one);
        uint32_t ba = __ballot_sync(0xffffffffu, (int)(o0a ^ o1a) >= 0);
        uint32_t bb = __ballot_sync(0xffffffffu, (int)(o0b ^ o1b) >= 0);
        if (lane == 0u) {
            g_mask[(i0 >> 5)]      = ba;
            g_mask[(i0 >> 5) + 1u] = bb;
        }
    }
}

// ---------------------------------------------------------------------------
// Prep: bf16 hi/lo split of scaled Q concat, K concat, and V=v1+v2.
// ---------------------------------------------------------------------------
__device__ __forceinline__ void split4(float4 v, uint2& hi, uint2& lo) {
    __nv_bfloat16 h0 = __float2bfloat16_rn(v.x);
    __nv_bfloat16 h1 = __float2bfloat16_rn(v.y);
    __nv_bfloat16 h2 = __float2bfloat16_rn(v.z);
    __nv_bfloat16 h3 = __float2bfloat16_rn(v.w);
    __nv_bfloat16 l0 = __float2bfloat16_rn(v.x - __bfloat162float(h0));
    __nv_bfloat16 l1 = __float2bfloat16_rn(v.y - __bfloat162float(h1));
    __nv_bfloat16 l2 = __float2bfloat16_rn(v.z - __bfloat162float(h2));
    __nv_bfloat16 l3 = __float2bfloat16_rn(v.w - __bfloat162float(h3));
    hi.x = (uint32_t)*(uint16_t*)&h0 | ((uint32_t)*(uint16_t*)&h1 << 16);
    hi.y = (uint32_t)*(uint16_t*)&h2 | ((uint32_t)*(uint16_t*)&h3 << 16);
    lo.x = (uint32_t)*(uint16_t*)&l0 | ((uint32_t)*(uint16_t*)&l1 << 16);
    lo.y = (uint32_t)*(uint16_t*)&l2 | ((uint32_t)*(uint16_t*)&l3 << 16);
}

__global__ void __launch_bounds__(256) prep_kernel(
    const float* __restrict__ q1, const float* __restrict__ q2,
    const float* __restrict__ k1, const float* __restrict__ k2,
    const float* __restrict__ v1, const float* __restrict__ v2)
{
    const int idx4 = blockIdx.x * 256 + threadIdx.x;
    const int row  = idx4 >> 4;
    const int d4   = idx4 & 15;
    const float4 a1 = ((const float4*)q1)[idx4];
    const float4 a2 = ((const float4*)q2)[idx4];
    const float4 b1 = ((const float4*)k1)[idx4];
    const float4 b2 = ((const float4*)k2)[idx4];
    const float4 c1 = ((const float4*)v1)[idx4];
    const float4 c2 = ((const float4*)v2)[idx4];
    const float s = 0.125f;
    float4 sa1 = make_float4(a1.x*s, a1.y*s, a1.z*s, a1.w*s);
    float4 sa2 = make_float4(a2.x*s, a2.y*s, a2.z*s, a2.w*s);
    uint2 hi, lo;
    const int qb = row * 128 + d4 * 4;
    split4(sa1, hi, lo);
    *(uint2*)(gQh + qb) = hi;      *(uint2*)(gQl + qb) = lo;
    split4(sa2, hi, lo);
    *(uint2*)(gQh + qb + 64) = hi; *(uint2*)(gQl + qb + 64) = lo;
    split4(b1, hi, lo);
    *(uint2*)(gKh + qb) = hi;      *(uint2*)(gKl + qb) = lo;
    split4(b2, hi, lo);
    *(uint2*)(gKh + qb + 64) = hi; *(uint2*)(gKl + qb + 64) = lo;
    float4 vs = make_float4(c1.x+c2.x, c1.y+c2.y, c1.z+c2.z, c1.w+c2.w);
    split4(vs, hi, lo);
    *(uint2*)(gVh + row * 64 + d4 * 4) = hi;
    *(uint2*)(gVl + row * 64 + d4 * 4) = lo;
}

// ---------------------------------------------------------------------------
// mma.sync helpers
// ---------------------------------------------------------------------------
__device__ __forceinline__ void ldsm_x4(uint32_t& r0, uint32_t& r1,
                                        uint32_t& r2, uint32_t& r3, uint32_t addr) {
    asm volatile("ldmatrix.sync.aligned.m8n8.x4.shared.b16 {%0,%1,%2,%3}, [%4];"
                 : "=r"(r0), "=r"(r1), "=r"(r2), "=r"(r3) : "r"(addr));
}
__device__ __forceinline__ void ldsm_x4_t(uint32_t& r0, uint32_t& r1,
                                          uint32_t& r2, uint32_t& r3, uint32_t addr) {
    asm volatile("ldmatrix.sync.aligned.m8n8.x4.trans.shared.b16 {%0,%1,%2,%3}, [%4];"
                 : "=r"(r0), "=r"(r1), "=r"(r2), "=r"(r3) : "r"(addr));
}
__device__ __forceinline__ void mma_bf16(float* c, const uint32_t* a,
                                         uint32_t b0, uint32_t b1) {
    asm volatile("mma.sync.aligned.m16n8k16.row.col.f32.bf16.bf16.f32 "
                 "{%0,%1,%2,%3}, {%4,%5,%6,%7}, {%8,%9}, {%0,%1,%2,%3};"
                 : "+f"(c[0]), "+f"(c[1]), "+f"(c[2]), "+f"(c[3])
                 : "r"(a[0]), "r"(a[1]), "r"(a[2]), "r"(a[3]), "r"(b0), "r"(b1));
}

// pack two fp32 into bf16x2 (low = x0) and compute the bf16x2 residual
__device__ __forceinline__ void split_pack(float x0, float x1,
                                           uint32_t& hi, uint32_t& lo) {
    uint32_t h;
    asm("cvt.rn.bf16x2.f32 %0, %1, %2;" : "=r"(h) : "f"(x1), "f"(x0));
    float h0 = __uint_as_float(h << 16);
    float h1 = __uint_as_float(h & 0xffff0000u);
    float r0 = x0 - h0, r1 = x1 - h1;
    uint32_t l;
    asm("cvt.rn.bf16x2.f32 %0, %1, %2;" : "=r"(l) : "f"(r1), "f"(r0));
    hi = h; lo = l;
}

// smem swizzles (bf16 element offsets). 128-wide rows (Q/K), 64-wide (V).
__device__ __forceinline__ int swb(int r, int ch) { return r * 128 + ((ch ^ (r & 7)) << 3); }
__device__ __forceinline__ int swv(int r, int ch) { return r * 64  + ((ch ^ (r & 7)) << 3); }

// ---------------------------------------------------------------------------
// FA2-style flash attention: QK and PV both on tensor cores (bf16 hi/lo, 3 MMAs).
// Softmax + dropout in fragment domain. BR=BC=64, 256 threads.
// Warp (w_r, w_c): 16-row block w_r, 32-col t-slice w_c. Partner warps (w_c=0/1)
// hold partial O over their t-slice; summed once in the epilogue.
// ---------------------------------------------------------------------------
__global__ void __launch_bounds__(256, 2) attn_kernel(float* __restrict__ out)
{
    extern __shared__ char smem[];
    __nv_bfloat16* sQh = (__nv_bfloat16*)(smem);            // 16 KB
    __nv_bfloat16* sQl = (__nv_bfloat16*)(smem + 16384);
    __nv_bfloat16* sKh = (__nv_bfloat16*)(smem + 32768);
    __nv_bfloat16* sKl = (__nv_bfloat16*)(smem + 49152);
    __nv_bfloat16* sVh = (__nv_bfloat16*)(smem + 65536);    // 8 KB
    __nv_bfloat16* sVl = (__nv_bfloat16*)(smem + 73728);
    float* sMax = (float*)(smem + 81920);                   // [2][64]
    float* sSum = (float*)(smem + 82432);                   // [2][64]

    const int tid = threadIdx.x;
    const int lane = tid & 31;
    const int w    = tid >> 5;
    const int w_r  = w & 3;
    const int w_c  = w >> 2;
    const int bh  = blockIdx.y;
    const int s0  = blockIdx.x << 6;
    const size_t rowbase128 = (size_t)bh * SS * 128;
    const size_t rowbase64  = (size_t)bh * SS * 64;

    // ---- load Q tile (bf16 hi/lo, swizzled) once ----
    {
        const uint4* gh = (const uint4*)(gQh + rowbase128 + (size_t)s0 * 128);
        const uint4* gl = (const uint4*)(gQl + rowbase128 + (size_t)s0 * 128);
        for (int it = tid; it < 1024; it += 256) {
            int r = it >> 4, ch = it & 15;
            int off = swb(r, ch);
            *(uint4*)(sQh + off) = gh[r * 16 + ch];
            *(uint4*)(sQl + off) = gl[r * 16 + ch];
        }
    }

    const uint32_t sQh_a = (uint32_t)__cvta_generic_to_shared(sQh);
    const uint32_t sQl_a = (uint32_t)__cvta_generic_to_shared(sQl);
    const uint32_t sKh_a = (uint32_t)__cvta_generic_to_shared(sKh);
    const uint32_t sKl_a = (uint32_t)__cvta_generic_to_shared(sKl);
    const uint32_t sVh_a = (uint32_t)__cvta_generic_to_shared(sVh);
    const uint32_t sVl_a = (uint32_t)__cvta_generic_to_shared(sVl);

    const int arow  = 16 * w_r + (lane & 15);
    const int g     = lane >> 3;
    const int brow0 = 32 * w_c + 8 * (g >> 1) + (lane & 7);
    const int brow1 = brow0 + 16;
    const int bpar  = g & 1;

    const int row0 = 16 * w_r + (lane >> 2);
    const int row1 = row0 + 8;
    const uint32_t mbase = ((uint32_t)bh << 17) + ((uint32_t)s0 << 6);

    float m00 = -3.0e38f, m01 = -3.0e38f, l00 = 0.0f, l01 = 0.0f;
    float o[8][4];
#pragma unroll
    for (int nb = 0; nb < 8; nb++)
#pragma unroll
        for (int i = 0; i < 4; i++) o[nb][i] = 0.0f;

    for (int t0 = 0; t0 < SS; t0 += 64) {
        // ---- load K (bf16 hi/lo) and V (bf16 hi/lo) tiles ----
        {
            const uint4* gh = (const uint4*)(gKh + rowbase128 + (size_t)t0 * 128);
            const uint4* gl = (const uint4*)(gKl + rowbase128 + (size_t)t0 * 128);
            for (int it = tid; it < 1024; it += 256) {
                int r = it >> 4, ch = it & 15;
                int off = swb(r, ch);
                *(uint4*)(sKh + off) = gh[r * 16 + ch];
                *(uint4*)(sKl + off) = gl[r * 16 + ch];
            }
            const uint4* gvh = (const uint4*)(gVh + rowbase64 + (size_t)t0 * 64);
            const uint4* gvl = (const uint4*)(gVl + rowbase64 + (size_t)t0 * 64);
            for (int it = tid; it < 512; it += 256) {
                int r = it >> 3, ch = it & 7;
                int off = swv(r, ch);
                *(uint4*)(sVh + off) = gvh[r * 8 + ch];
                *(uint4*)(sVl + off) = gvl[r * 8 + ch];
            }
        }
        __syncthreads();

        // ---- S fragments (warp tile 16x32) via 3-split bf16 MMAs ----
        float cfr[4][4];
#pragma unroll
        for (int nb = 0; nb < 4; nb++)
#pragma unroll
            for (int i = 0; i < 4; i++) cfr[nb][i] = 0.0f;

#pragma unroll
        for (int kb = 0; kb < 8; kb++) {
            const int ach = 2 * kb + (lane >> 4);
            const uint32_t aoff = (uint32_t)(swb(arow, ach) * 2);
            uint32_t qh[4], ql[4];
            ldsm_x4(qh[0], qh[1], qh[2], qh[3], sQh_a + aoff);
            ldsm_x4(ql[0], ql[1], ql[2], ql[3], sQl_a + aoff);

            const int bch = 2 * kb + bpar;
            const uint32_t b0off = (uint32_t)(swb(brow0, bch) * 2);
            const uint32_t b1off = (uint32_t)(swb(brow1, bch) * 2);
            uint32_t kh0[4], kl0[4], kh1[4], kl1[4];
            ldsm_x4(kh0[0], kh0[1], kh0[2], kh0[3], sKh_a + b0off);
            ldsm_x4(kl0[0], kl0[1], kl0[2], kl0[3], sKl_a + b0off);
            ldsm_x4(kh1[0], kh1[1], kh1[2], kh1[3], sKh_a + b1off);
            ldsm_x4(kl1[0], kl1[1], kl1[2], kl1[3], sKl_a + b1off);

            mma_bf16(cfr[0], qh, kh0[0], kh0[1]);
            mma_bf16(cfr[0], qh, kl0[0], kl0[1]);
            mma_bf16(cfr[0], ql, kh0[0], kh0[1]);
            mma_bf16(cfr[1], qh, kh0[2], kh0[3]);
            mma_bf16(cfr[1], qh, kl0[2], kl0[3]);
            mma_bf16(cfr[1], ql, kh0[2], kh0[3]);
            mma_bf16(cfr[2], qh, kh1[0], kh1[1]);
            mma_bf16(cfr[2], qh, kl1[0], kl1[1]);
            mma_bf16(cfr[2], ql, kh1[0], kh1[1]);
            mma_bf16(cfr[3], qh, kh1[2], kh1[3]);
            mma_bf16(cfr[3], qh, kl1[2], kl1[3]);
            mma_bf16(cfr[3], ql, kh1[2], kh1[3]);
        }

        // ---- fragment-domain online softmax ----
        float mx0 = fmaxf(fmaxf(cfr[0][0], cfr[0][1]), fmaxf(cfr[1][0], cfr[1][1]));
        mx0 = fmaxf(mx0, fmaxf(fmaxf(cfr[2][0], cfr[2][1]), fmaxf(cfr[3][0], cfr[3][1])));
        float mx1 = fmaxf(fmaxf(cfr[0][2], cfr[0][3]), fmaxf(cfr[1][2], cfr[1][3]));
        mx1 = fmaxf(mx1, fmaxf(fmaxf(cfr[2][2], cfr[2][3]), fmaxf(cfr[3][2], cfr[3][3])));
        mx0 = fmaxf(mx0, __shfl_xor_sync(0xffffffffu, mx0, 1));
        mx0 = fmaxf(mx0, __shfl_xor_sync(0xffffffffu, mx0, 2));
        mx1 = fmaxf(mx1, __shfl_xor_sync(0xffffffffu, mx1, 1));
        mx1 = fmaxf(mx1, __shfl_xor_sync(0xffffffffu, mx1, 2));
        if ((lane & 3) == 0) {
            sMax[w_c * 64 + row0] = mx0;
            sMax[w_c * 64 + row1] = mx1;
        }
        __syncthreads();

        const float newm0 = fmaxf(m00, fmaxf(sMax[row0], sMax[64 + row0]));
        const float newm1 = fmaxf(m01, fmaxf(sMax[row1], sMax[64 + row1]));
        const float f0 = __expf(m00 - newm0);
        const float f1 = __expf(m01 - newm1);

        const uint32_t wb = (uint32_t)(t0 >> 5) + (uint32_t)w_c;
        const uint32_t wm0 = g_mask[mbase + ((uint32_t)row0 << 6) + wb];
        const uint32_t wm1 = g_mask[mbase + ((uint32_t)row1 << 6) + wb];

        float rs0 = 0.0f, rs1 = 0.0f;
        const int bsh = 2 * (lane & 3);
#pragma unroll
        for (int nb = 0; nb < 4; nb++) {
            const int sh = 8 * nb + bsh;
            float p0 = __expf(cfr[nb][0] - newm0); rs0 += p0;
            float p1 = __expf(cfr[nb][1] - newm0); rs0 += p1;
            float p2 = __expf(cfr[nb][2] - newm1); rs1 += p2;
            float p3 = __expf(cfr[nb][3] - newm1); rs1 += p3;
            cfr[nb][0] = ((wm0 >> sh)       & 1u) ? p0 : 0.0f;
            cfr[nb][1] = ((wm0 >> (sh + 1)) & 1u) ? p1 : 0.0f;
            cfr[nb][2] = ((wm1 >> sh)       & 1u) ? p2 : 0.0f;
            cfr[nb][3] = ((wm1 >> (sh + 1)) & 1u) ? p3 : 0.0f;
        }
        rs0 += __shfl_xor_sync(0xffffffffu, rs0, 1);
        rs0 += __shfl_xor_sync(0xffffffffu, rs0, 2);
        rs1 += __shfl_xor_sync(0xffffffffu, rs1, 1);
        rs1 += __shfl_xor_sync(0xffffffffu, rs1, 2);
        if ((lane & 3) == 0) {
            sSum[w_c * 64 + row0] = rs0;
            sSum[w_c * 64 + row1] = rs1;
        }

        // rescale partial O fragments
#pragma unroll
        for (int nb = 0; nb < 8; nb++) {
            o[nb][0] *= f0; o[nb][1] *= f0;
            o[nb][2] *= f1; o[nb][3] *= f1;
        }

        // ---- PV: P (registers) x V (ldmatrix.trans), 3-split bf16 MMAs ----
#pragma unroll
        for (int kb2 = 0; kb2 < 2; kb2++) {
            uint32_t ah[4], al[4];
            split_pack(cfr[2*kb2][0],   cfr[2*kb2][1],   ah[0], al[0]);
            split_pack(cfr[2*kb2][2],   cfr[2*kb2][3],   ah[1], al[1]);
            split_pack(cfr[2*kb2+1][0], cfr[2*kb2+1][1], ah[2], al[2]);
            split_pack(cfr[2*kb2+1][2], cfr[2*kb2+1][3], ah[3], al[3]);
            const int vkrow = 32 * w_c + 16 * kb2 + (lane & 15);
#pragma unroll
            for (int nb16 = 0; nb16 < 4; nb16++) {
                const int ch = 2 * nb16 + (lane >> 4);
                const uint32_t voff = (uint32_t)(swv(vkrow, ch) * 2);
                uint32_t vh[4], vl[4];
                ldsm_x4_t(vh[0], vh[1], vh[2], vh[3], sVh_a + voff);
                ldsm_x4_t(vl[0], vl[1], vl[2], vl[3], sVl_a + voff);
                mma_bf16(o[2*nb16],     ah, vh[0], vh[1]);
                mma_bf16(o[2*nb16],     ah, vl[0], vl[1]);
                mma_bf16(o[2*nb16],     al, vh[0], vh[1]);
                mma_bf16(o[2*nb16+1],   ah, vh[2], vh[3]);
                mma_bf16(o[2*nb16+1],   ah, vl[2], vl[3]);
                mma_bf16(o[2*nb16+1],   al, vh[2], vh[3]);
            }
        }
        __syncthreads();

        l00 = l00 * f0 + sSum[row0] + sSum[64 + row0];
        l01 = l01 * f1 + sSum[row1] + sSum[64 + row1];
        m00 = newm0; m01 = newm1;
    }

    // ---- epilogue: sum partner-warp partials, scale by 2/l, store ----
    float* sO = (float*)smem;   // reuse Q area (all Q reads complete)
    if (w_c == 1) {
#pragma unroll
        for (int nb = 0; nb < 8; nb++) {
            const int col = 8 * nb + 2 * (lane & 3);
            *(float2*)(sO + row0 * 64 + col) = make_float2(o[nb][0], o[nb][1]);
            *(float2*)(sO + row1 * 64 + col) = make_float2(o[nb][2], o[nb][3]);
        }
    }
    __syncthreads();
    if (w_c == 0) {
        const float inv0 = 2.0f / l00;
        const float inv1 = 2.0f / l01;
        float* obase = out + (size_t)bh * SS * DD;
#pragma unroll
        for (int nb = 0; nb < 8; nb++) {
            const int col = 8 * nb + 2 * (lane & 3);
            float2 q0 = *(float2*)(sO + row0 * 64 + col);
            float2 q1 = *(float2*)(sO + row1 * 64 + col);
            float2 r0 = make_float2((o[nb][0] + q0.x) * inv0, (o[nb][1] + q0.y) * inv0);
            float2 r1 = make_float2((o[nb][2] + q1.x) * inv1, (o[nb][3] + q1.y) * inv1);
            *(float2*)(obase + (size_t)(s0 + row0) * DD + col) = r0;
            *(float2*)(obase + (size_t)(s0 + row1) * DD + col) = r1;
        }
    }
}

// ---------------------------------------------------------------------------
extern "C" void kernel_launch(void* const* d_in, const int* in_sizes, int n_in,
                              void* d_out, int out_size) {
    (void)in_sizes; (void)n_in; (void)out_size;
    const float* q1 = (const float*)d_in[0];
    const float* q2 = (const float*)d_in[1];
    const float* k1 = (const float*)d_in[2];
    const float* k2 = (const float*)d_in[3];
    const float* v1 = (const float*)d_in[4];
    const float* v2 = (const float*)d_in[5];
    float* out = (float*)d_out;

    mask_kernel<<<2048, 256>>>();
    prep_kernel<<<(NBH * SS * DD / 4) / 256, 256>>>(q1, q2, k1, k2, v1, v2);

    const int smem_bytes = 82944;
    cudaFuncSetAttribute(attn_kernel,
                         cudaFuncAttributeMaxDynamicSharedMemorySize, smem_bytes);
    attn_kernel<<<dim3(SS / 64, NBH), 256, smem_bytes>>>(out);
}

// round 7
// speedup vs baseline: 1.9806x; 1.1265x over previous
#include <cuda_runtime.h>
#include <cuda_bf16.h>
#include <cstdint>

// Problem constants
#define SS   2048
#define DD   64
#define NBH  32            // B*H = 2*16

// Static device scratch (no allocs allowed)
__device__ __nv_bfloat16 gQh[NBH * SS * 128];         // scaled Q concat, hi
__device__ __nv_bfloat16 gQl[NBH * SS * 128];         // lo
__device__ __nv_bfloat16 gKh[NBH * SS * 128];         // K concat, hi
__device__ __nv_bfloat16 gKl[NBH * SS * 128];         // lo
__device__ __nv_bfloat16 gVh[NBH * SS * 64];          // v1+v2, hi
__device__ __nv_bfloat16 gVl[NBH * SS * 64];          // lo

// ---------------------------------------------------------------------------
// threefry2x32, key (0, 42); partitionable bitstream: bits = out0 ^ out1.
// Dual-interleaved (2 independent calls) to cover the 4-cyc RAW chain.
// c0 == 0 always (element index < 2^32), so x0 init is a constant.
// ---------------------------------------------------------------------------
#define TF_K0 0u
#define TF_K1 42u
#define TF_K2 (0x1BD11BDAu ^ TF_K0 ^ TF_K1)

__device__ __forceinline__ void threefry_dual(uint32_t cA, uint32_t cB,
                                              uint32_t& oA, uint32_t& oB) {
    uint32_t a0 = TF_K0, a1 = cA + TF_K1;
    uint32_t b0 = TF_K0, b1 = cB + TF_K1;
#define R2(r) { a0 += a1; a1 = __funnelshift_l(a1, a1, (r)); a1 ^= a0; \
                b0 += b1; b1 = __funnelshift_l(b1, b1, (r)); b1 ^= b0; }
    R2(13) R2(15) R2(26) R2(6)
    a0 += TF_K1; a1 += TF_K2 + 1u;  b0 += TF_K1; b1 += TF_K2 + 1u;
    R2(17) R2(29) R2(16) R2(24)
    a0 += TF_K2; a1 += TF_K0 + 2u;  b0 += TF_K2; b1 += TF_K0 + 2u;
    R2(13) R2(15) R2(26) R2(6)
    a0 += TF_K0; a1 += TF_K1 + 3u;  b0 += TF_K0; b1 += TF_K1 + 3u;
    R2(17) R2(29) R2(16) R2(24)
    a0 += TF_K1; a1 += TF_K2 + 4u;  b0 += TF_K1; b1 += TF_K2 + 4u;
    R2(13) R2(15) R2(26) R2(6)
    a0 += TF_K2; a1 += TF_K0 + 5u;  b0 += TF_K2; b1 += TF_K0 + 5u;
#undef R2
    oA = a0 ^ a1; oB = b0 ^ b1;
}

// ---------------------------------------------------------------------------
// Prep: bf16 hi/lo split of scaled Q concat, K concat, and V=v1+v2.
// ---------------------------------------------------------------------------
__device__ __forceinline__ void split4(float4 v, uint2& hi, uint2& lo) {
    __nv_bfloat16 h0 = __float2bfloat16_rn(v.x);
    __nv_bfloat16 h1 = __float2bfloat16_rn(v.y);
    __nv_bfloat16 h2 = __float2bfloat16_rn(v.z);
    __nv_bfloat16 h3 = __float2bfloat16_rn(v.w);
    __nv_bfloat16 l0 = __float2bfloat16_rn(v.x - __bfloat162float(h0));
    __nv_bfloat16 l1 = __float2bfloat16_rn(v.y - __bfloat162float(h1));
    __nv_bfloat16 l2 = __float2bfloat16_rn(v.z - __bfloat162float(h2));
    __nv_bfloat16 l3 = __float2bfloat16_rn(v.w - __bfloat162float(h3));
    hi.x = (uint32_t)*(uint16_t*)&h0 | ((uint32_t)*(uint16_t*)&h1 << 16);
    hi.y = (uint32_t)*(uint16_t*)&h2 | ((uint32_t)*(uint16_t*)&h3 << 16);
    lo.x = (uint32_t)*(uint16_t*)&l0 | ((uint32_t)*(uint16_t*)&l1 << 16);
    lo.y = (uint32_t)*(uint16_t*)&l2 | ((uint32_t)*(uint16_t*)&l3 << 16);
}

__global__ void __launch_bounds__(256) prep_kernel(
    const float* __restrict__ q1, const float* __restrict__ q2,
    const float* __restrict__ k1, const float* __restrict__ k2,
    const float* __restrict__ v1, const float* __restrict__ v2)
{
    const int idx4 = blockIdx.x * 256 + threadIdx.x;
    const int row  = idx4 >> 4;
    const int d4   = idx4 & 15;
    const float4 a1 = ((const float4*)q1)[idx4];
    const float4 a2 = ((const float4*)q2)[idx4];
    const float4 b1 = ((const float4*)k1)[idx4];
    const float4 b2 = ((const float4*)k2)[idx4];
    const float4 c1 = ((const float4*)v1)[idx4];
    const float4 c2 = ((const float4*)v2)[idx4];
    const float s = 0.125f;
    float4 sa1 = make_float4(a1.x*s, a1.y*s, a1.z*s, a1.w*s);
    float4 sa2 = make_float4(a2.x*s, a2.y*s, a2.z*s, a2.w*s);
    uint2 hi, lo;
    const int qb = row * 128 + d4 * 4;
    split4(sa1, hi, lo);
    *(uint2*)(gQh + qb) = hi;      *(uint2*)(gQl + qb) = lo;
    split4(sa2, hi, lo);
    *(uint2*)(gQh + qb + 64) = hi; *(uint2*)(gQl + qb + 64) = lo;
    split4(b1, hi, lo);
    *(uint2*)(gKh + qb) = hi;      *(uint2*)(gKl + qb) = lo;
    split4(b2, hi, lo);
    *(uint2*)(gKh + qb + 64) = hi; *(uint2*)(gKl + qb + 64) = lo;
    float4 vs = make_float4(c1.x+c2.x, c1.y+c2.y, c1.z+c2.z, c1.w+c2.w);
    split4(vs, hi, lo);
    *(uint2*)(gVh + row * 64 + d4 * 4) = hi;
    *(uint2*)(gVl + row * 64 + d4 * 4) = lo;
}

// ---------------------------------------------------------------------------
// mma.sync helpers
// ---------------------------------------------------------------------------
__device__ __forceinline__ void ldsm_x4(uint32_t& r0, uint32_t& r1,
                                        uint32_t& r2, uint32_t& r3, uint32_t addr) {
    asm volatile("ldmatrix.sync.aligned.m8n8.x4.shared.b16 {%0,%1,%2,%3}, [%4];"
                 : "=r"(r0), "=r"(r1), "=r"(r2), "=r"(r3) : "r"(addr));
}
__device__ __forceinline__ void ldsm_x4_t(uint32_t& r0, uint32_t& r1,
                                          uint32_t& r2, uint32_t& r3, uint32_t addr) {
    asm volatile("ldmatrix.sync.aligned.m8n8.x4.trans.shared.b16 {%0,%1,%2,%3}, [%4];"
                 : "=r"(r0), "=r"(r1), "=r"(r2), "=r"(r3) : "r"(addr));
}
__device__ __forceinline__ void mma_bf16(float* c, const uint32_t* a,
                                         uint32_t b0, uint32_t b1) {
    asm volatile("mma.sync.aligned.m16n8k16.row.col.f32.bf16.bf16.f32 "
                 "{%0,%1,%2,%3}, {%4,%5,%6,%7}, {%8,%9}, {%0,%1,%2,%3};"
                 : "+f"(c[0]), "+f"(c[1]), "+f"(c[2]), "+f"(c[3])
                 : "r"(a[0]), "r"(a[1]), "r"(a[2]), "r"(a[3]), "r"(b0), "r"(b1));
}

// pack two fp32 into bf16x2 (low = x0) and compute the bf16x2 residual
__device__ __forceinline__ void split_pack(float x0, float x1,
                                           uint32_t& hi, uint32_t& lo) {
    uint32_t h;
    asm("cvt.rn.bf16x2.f32 %0, %1, %2;" : "=r"(h) : "f"(x1), "f"(x0));
    float h0 = __uint_as_float(h << 16);
    float h1 = __uint_as_float(h & 0xffff0000u);
    float r0 = x0 - h0, r1 = x1 - h1;
    uint32_t l;
    asm("cvt.rn.bf16x2.f32 %0, %1, %2;" : "=r"(l) : "f"(r1), "f"(r0));
    hi = h; lo = l;
}

// smem swizzles (bf16 element offsets). 128-wide rows (Q/K), 64-wide (V).
__device__ __forceinline__ int swb(int r, int ch) { return r * 128 + ((ch ^ (r & 7)) << 3); }
__device__ __forceinline__ int swv(int r, int ch) { return r * 64  + ((ch ^ (r & 7)) << 3); }

// ---------------------------------------------------------------------------
// Fused FA2 flash attention: QK and PV on tensor cores (bf16 hi/lo, 3 MMAs),
// threefry dropout mask generated IN-LOOP (ALU pipe overlaps tensor pipe).
// BR=BC=64, 256 threads. Warp (w_r, w_c): 16-row block, 32-col t-slice.
// ---------------------------------------------------------------------------
__global__ void __launch_bounds__(256, 2) attn_kernel(float* __restrict__ out)
{
    extern __shared__ char smem[];
    __nv_bfloat16* sQh = (__nv_bfloat16*)(smem);            // 16 KB
    __nv_bfloat16* sQl = (__nv_bfloat16*)(smem + 16384);
    __nv_bfloat16* sKh = (__nv_bfloat16*)(smem + 32768);
    __nv_bfloat16* sKl = (__nv_bfloat16*)(smem + 49152);
    __nv_bfloat16* sVh = (__nv_bfloat16*)(smem + 65536);    // 8 KB
    __nv_bfloat16* sVl = (__nv_bfloat16*)(smem + 73728);
    float* sMax = (float*)(smem + 81920);                   // [2][64]
    float* sSum = (float*)(smem + 82432);                   // [2][64]
    uint32_t* sMask = (uint32_t*)(smem + 82944);            // [64][2] words

    const int tid = threadIdx.x;
    const int lane = tid & 31;
    const int w    = tid >> 5;
    const int w_r  = w & 3;
    const int w_c  = w >> 2;
    const int bh  = blockIdx.y;
    const int s0  = blockIdx.x << 6;
    const size_t rowbase128 = (size_t)bh * SS * 128;
    const size_t rowbase64  = (size_t)bh * SS * 64;

    // ---- load Q tile (bf16 hi/lo, swizzled) once ----
    {
        const uint4* gh = (const uint4*)(gQh + rowbase128 + (size_t)s0 * 128);
        const uint4* gl = (const uint4*)(gQl + rowbase128 + (size_t)s0 * 128);
        for (int it = tid; it < 1024; it += 256) {
            int r = it >> 4, ch = it & 15;
            int off = swb(r, ch);
            *(uint4*)(sQh + off) = gh[r * 16 + ch];
            *(uint4*)(sQl + off) = gl[r * 16 + ch];
        }
    }

    const uint32_t sQh_a = (uint32_t)__cvta_generic_to_shared(sQh);
    const uint32_t sQl_a = (uint32_t)__cvta_generic_to_shared(sQl);
    const uint32_t sKh_a = (uint32_t)__cvta_generic_to_shared(sKh);
    const uint32_t sKl_a = (uint32_t)__cvta_generic_to_shared(sKl);
    const uint32_t sVh_a = (uint32_t)__cvta_generic_to_shared(sVh);
    const uint32_t sVl_a = (uint32_t)__cvta_generic_to_shared(sVl);

    const int arow  = 16 * w_r + (lane & 15);
    const int g     = lane >> 3;
    const int brow0 = 32 * w_c + 8 * (g >> 1) + (lane & 7);
    const int brow1 = brow0 + 16;
    const int bpar  = g & 1;

    const int row0 = 16 * w_r + (lane >> 2);
    const int row1 = row0 + 8;
    // flat mask element index base for this warp's first mask row (r = 8w+j)
    const uint32_t ibase0 = ((uint32_t)bh << 22) + (((uint32_t)(s0 + 8 * w)) << 11) + (uint32_t)lane;

    float m00 = -3.0e38f, m01 = -3.0e38f, l00 = 0.0f, l01 = 0.0f;
    float o[8][4];
#pragma unroll
    for (int nb = 0; nb < 8; nb++)
#pragma unroll
        for (int i = 0; i < 4; i++) o[nb][i] = 0.0f;

    for (int t0 = 0; t0 < SS; t0 += 64) {
        // ---- load K (bf16 hi/lo) and V (bf16 hi/lo) tiles ----
        {
            const uint4* gh = (const uint4*)(gKh + rowbase128 + (size_t)t0 * 128);
            const uint4* gl = (const uint4*)(gKl + rowbase128 + (size_t)t0 * 128);
            for (int it = tid; it < 1024; it += 256) {
                int r = it >> 4, ch = it & 15;
                int off = swb(r, ch);
                *(uint4*)(sKh + off) = gh[r * 16 + ch];
                *(uint4*)(sKl + off) = gl[r * 16 + ch];
            }
            const uint4* gvh = (const uint4*)(gVh + rowbase64 + (size_t)t0 * 64);
            const uint4* gvl = (const uint4*)(gVl + rowbase64 + (size_t)t0 * 64);
            for (int it = tid; it < 512; it += 256) {
                int r = it >> 3, ch = it & 7;
                int off = swv(r, ch);
                *(uint4*)(sVh + off) = gvh[r * 8 + ch];
                *(uint4*)(sVl + off) = gvl[r * 8 + ch];
            }
        }
        __syncthreads();

        // ---- generate this tile's dropout mask words (ALU work; overlaps
        //      other warps' tensor-pipe MMAs). Warp w makes rows 8w..8w+7. ----
        {
            const uint32_t ib = ibase0 + (uint32_t)t0;
#pragma unroll 1
            for (int j = 0; j < 8; j++) {
                uint32_t iA = ib + ((uint32_t)j << 11);
                uint32_t oA, oB;
                threefry_dual(iA, iA + 32u, oA, oB);
                uint32_t wA = __ballot_sync(0xffffffffu, (int)oA >= 0);
                uint32_t wB = __ballot_sync(0xffffffffu, (int)oB >= 0);
                if (lane == 0) {
                    sMask[16 * w + 2 * j]     = wA;
                    sMask[16 * w + 2 * j + 1] = wB;
                }
            }
        }

        // ---- S fragments (warp tile 16x32) via 3-split bf16 MMAs ----
        float cfr[4][4];
#pragma unroll
        for (int nb = 0; nb < 4; nb++)
#pragma unroll
            for (int i = 0; i < 4; i++) cfr[nb][i] = 0.0f;

#pragma unroll
        for (int kb = 0; kb < 8; kb++) {
            const int ach = 2 * kb + (lane >> 4);
            const uint32_t aoff = (uint32_t)(swb(arow, ach) * 2);
            uint32_t qh[4], ql[4];
            ldsm_x4(qh[0], qh[1], qh[2], qh[3], sQh_a + aoff);
            ldsm_x4(ql[0], ql[1], ql[2], ql[3], sQl_a + aoff);

            const int bch = 2 * kb + bpar;
            const uint32_t b0off = (uint32_t)(swb(brow0, bch) * 2);
            const uint32_t b1off = (uint32_t)(swb(brow1, bch) * 2);
            uint32_t kh0[4], kl0[4], kh1[4], kl1[4];
            ldsm_x4(kh0[0], kh0[1], kh0[2], kh0[3], sKh_a + b0off);
            ldsm_x4(kl0[0], kl0[1], kl0[2], kl0[3], sKl_a + b0off);
            ldsm_x4(kh1[0], kh1[1], kh1[2], kh1[3], sKh_a + b1off);
            ldsm_x4(kl1[0], kl1[1], kl1[2], kl1[3], sKl_a + b1off);

            mma_bf16(cfr[0], qh, kh0[0], kh0[1]);
            mma_bf16(cfr[0], qh, kl0[0], kl0[1]);
            mma_bf16(cfr[0], ql, kh0[0], kh0[1]);
            mma_bf16(cfr[1], qh, kh0[2], kh0[3]);
            mma_bf16(cfr[1], qh, kl0[2], kl0[3]);
            mma_bf16(cfr[1], ql, kh0[2], kh0[3]);
            mma_bf16(cfr[2], qh, kh1[0], kh1[1]);
            mma_bf16(cfr[2], qh, kl1[0], kl1[1]);
            mma_bf16(cfr[2], ql, kh1[0], kh1[1]);
            mma_bf16(cfr[3], qh, kh1[2], kh1[3]);
            mma_bf16(cfr[3], qh, kl1[2], kl1[3]);
            mma_bf16(cfr[3], ql, kh1[2], kh1[3]);
        }

        // ---- fragment-domain online softmax ----
        float mx0 = fmaxf(fmaxf(cfr[0][0], cfr[0][1]), fmaxf(cfr[1][0], cfr[1][1]));
        mx0 = fmaxf(mx0, fmaxf(fmaxf(cfr[2][0], cfr[2][1]), fmaxf(cfr[3][0], cfr[3][1])));
        float mx1 = fmaxf(fmaxf(cfr[0][2], cfr[0][3]), fmaxf(cfr[1][2], cfr[1][3]));
        mx1 = fmaxf(mx1, fmaxf(fmaxf(cfr[2][2], cfr[2][3]), fmaxf(cfr[3][2], cfr[3][3])));
        mx0 = fmaxf(mx0, __shfl_xor_sync(0xffffffffu, mx0, 1));
        mx0 = fmaxf(mx0, __shfl_xor_sync(0xffffffffu, mx0, 2));
        mx1 = fmaxf(mx1, __shfl_xor_sync(0xffffffffu, mx1, 1));
        mx1 = fmaxf(mx1, __shfl_xor_sync(0xffffffffu, mx1, 2));
        if ((lane & 3) == 0) {
            sMax[w_c * 64 + row0] = mx0;
            sMax[w_c * 64 + row1] = mx1;
        }
        __syncthreads();

        const float newm0 = fmaxf(m00, fmaxf(sMax[row0], sMax[64 + row0]));
        const float newm1 = fmaxf(m01, fmaxf(sMax[row1], sMax[64 + row1]));
        const float f0 = __expf(m00 - newm0);
        const float f1 = __expf(m01 - newm1);

        const uint32_t wm0 = sMask[2 * row0 + w_c];
        const uint32_t wm1 = sMask[2 * row1 + w_c];

        float rs0 = 0.0f, rs1 = 0.0f;
        const int bsh = 2 * (lane & 3);
#pragma unroll
        for (int nb = 0; nb < 4; nb++) {
            const int sh = 8 * nb + bsh;
            float p0 = __expf(cfr[nb][0] - newm0); rs0 += p0;
            float p1 = __expf(cfr[nb][1] - newm0); rs0 += p1;
            float p2 = __expf(cfr[nb][2] - newm1); rs1 += p2;
            float p3 = __expf(cfr[nb][3] - newm1); rs1 += p3;
            cfr[nb][0] = ((wm0 >> sh)       & 1u) ? p0 : 0.0f;
            cfr[nb][1] = ((wm0 >> (sh + 1)) & 1u) ? p1 : 0.0f;
            cfr[nb][2] = ((wm1 >> sh)       & 1u) ? p2 : 0.0f;
            cfr[nb][3] = ((wm1 >> (sh + 1)) & 1u) ? p3 : 0.0f;
        }
        rs0 += __shfl_xor_sync(0xffffffffu, rs0, 1);
        rs0 += __shfl_xor_sync(0xffffffffu, rs0, 2);
        rs1 += __shfl_xor_sync(0xffffffffu, rs1, 1);
        rs1 += __shfl_xor_sync(0xffffffffu, rs1, 2);
        if ((lane & 3) == 0) {
            sSum[w_c * 64 + row0] = rs0;
            sSum[w_c * 64 + row1] = rs1;
        }

        // rescale partial O fragments
#pragma unroll
        for (int nb = 0; nb < 8; nb++) {
            o[nb][0] *= f0; o[nb][1] *= f0;
            o[nb][2] *= f1; o[nb][3] *= f1;
        }

        // ---- PV: P (registers) x V (ldmatrix.trans), 3-split bf16 MMAs ----
#pragma unroll
        for (int kb2 = 0; kb2 < 2; kb2++) {
            uint32_t ah[4], al[4];
            split_pack(cfr[2*kb2][0],   cfr[2*kb2][1],   ah[0], al[0]);
            split_pack(cfr[2*kb2][2],   cfr[2*kb2][3],   ah[1], al[1]);
            split_pack(cfr[2*kb2+1][0], cfr[2*kb2+1][1], ah[2], al[2]);
            split_pack(cfr[2*kb2+1][2], cfr[2*kb2+1][3], ah[3], al[3]);
            const int vkrow = 32 * w_c + 16 * kb2 + (lane & 15);
#pragma unroll
            for (int nb16 = 0; nb16 < 4; nb16++) {
                const int ch = 2 * nb16 + (lane >> 4);
                const uint32_t voff = (uint32_t)(swv(vkrow, ch) * 2);
                uint32_t vh[4], vl[4];
                ldsm_x4_t(vh[0], vh[1], vh[2], vh[3], sVh_a + voff);
                ldsm_x4_t(vl[0], vl[1], vl[2], vl[3], sVl_a + voff);
                mma_bf16(o[2*nb16],     ah, vh[0], vh[1]);
                mma_bf16(o[2*nb16],     ah, vl[0], vl[1]);
                mma_bf16(o[2*nb16],     al, vh[0], vh[1]);
                mma_bf16(o[2*nb16+1],   ah, vh[2], vh[3]);
                mma_bf16(o[2*nb16+1],   ah, vl[2], vl[3]);
                mma_bf16(o[2*nb16+1],   al, vh[2], vh[3]);
            }
        }
        __syncthreads();

        l00 = l00 * f0 + sSum[row0] + sSum[64 + row0];
        l01 = l01 * f1 + sSum[row1] + sSum[64 + row1];
        m00 = newm0; m01 = newm1;
    }

    // ---- epilogue: sum partner-warp partials, scale by 2/l, store ----
    float* sO = (float*)smem;   // reuse Q area (all Q reads complete)
    if (w_c == 1) {
#pragma unroll
        for (int nb = 0; nb < 8; nb++) {
            const int col = 8 * nb + 2 * (lane & 3);
            *(float2*)(sO + row0 * 64 + col) = make_float2(o[nb][0], o[nb][1]);
            *(float2*)(sO + row1 * 64 + col) = make_float2(o[nb][2], o[nb][3]);
        }
    }
    __syncthreads();
    if (w_c == 0) {
        const float inv0 = 2.0f / l00;
        const float inv1 = 2.0f / l01;
        float* obase = out + (size_t)bh * SS * DD;
#pragma unroll
        for (int nb = 0; nb < 8; nb++) {
            const int col = 8 * nb + 2 * (lane & 3);
            float2 q0 = *(float2*)(sO + row0 * 64 + col);
            float2 q1 = *(float2*)(sO + row1 * 64 + col);
            float2 r0 = make_float2((o[nb][0] + q0.x) * inv0, (o[nb][1] + q0.y) * inv0);
            float2 r1 = make_float2((o[nb][2] + q1.x) * inv1, (o[nb][3] + q1.y) * inv1);
            *(float2*)(obase + (size_t)(s0 + row0) * DD + col) = r0;
            *(float2*)(obase + (size_t)(s0 + row1) * DD + col) = r1;
        }
    }
}

// ---------------------------------------------------------------------------
extern "C" void kernel_launch(void* const* d_in, const int* in_sizes, int n_in,
                              void* d_out, int out_size) {
    (void)in_sizes; (void)n_in; (void)out_size;
    const float* q1 = (const float*)d_in[0];
    const float* q2 = (const float*)d_in[1];
    const float* k1 = (const float*)d_in[2];
    const float* k2 = (const float*)d_in[3];
    const float* v1 = (const float*)d_in[4];
    const float* v2 = (const float*)d_in[5];
    float* out = (float*)d_out;

    prep_kernel<<<(NBH * SS * DD / 4) / 256, 256>>>(q1, q2, k1, k2, v1, v2);

    const int smem_bytes = 83456;
    cudaFuncSetAttribute(attn_kernel,
                         cudaFuncAttributeMaxDynamicSharedMemorySize, smem_bytes);
    attn_kernel<<<dim3(SS / 64, NBH), 256, smem_bytes>>>(out);
}

// round 9
// speedup vs baseline: 2.9789x; 1.5041x over previous
#include <cuda_runtime.h>
#include <cuda_fp16.h>
#include <cuda_bf16.h>
#include <cstdint>

// Problem constants
#define SS   2048
#define DD   64
#define NBH  32            // B*H = 2*16

// Static device scratch (no allocs allowed)
__device__ __half        gQ[NBH * SS * 128];          // scaled q1||q2, fp16
__device__ __half        gK[NBH * SS * 128];          // k1||k2, fp16
__device__ __nv_bfloat16 gVh[NBH * SS * 64];          // v1+v2, bf16 hi
__device__ __nv_bfloat16 gVl[NBH * SS * 64];          // bf16 lo

// ---------------------------------------------------------------------------
// threefry2x32, key (0, 42); partitionable bitstream: bits = out0 ^ out1.
// Dual-interleaved (2 independent calls) to cover the 4-cyc RAW chain.
// ---------------------------------------------------------------------------
#define TF_K0 0u
#define TF_K1 42u
#define TF_K2 (0x1BD11BDAu ^ TF_K0 ^ TF_K1)

__device__ __forceinline__ void threefry_dual(uint32_t cA, uint32_t cB,
                                              uint32_t& oA, uint32_t& oB) {
    uint32_t a0 = TF_K0, a1 = cA + TF_K1;
    uint32_t b0 = TF_K0, b1 = cB + TF_K1;
#define R2(r) { a0 += a1; a1 = __funnelshift_l(a1, a1, (r)); a1 ^= a0; \
                b0 += b1; b1 = __funnelshift_l(b1, b1, (r)); b1 ^= b0; }
    R2(13) R2(15) R2(26) R2(6)
    a0 += TF_K1; a1 += TF_K2 + 1u;  b0 += TF_K1; b1 += TF_K2 + 1u;
    R2(17) R2(29) R2(16) R2(24)
    a0 += TF_K2; a1 += TF_K0 + 2u;  b0 += TF_K2; b1 += TF_K0 + 2u;
    R2(13) R2(15) R2(26) R2(6)
    a0 += TF_K0; a1 += TF_K1 + 3u;  b0 += TF_K0; b1 += TF_K1 + 3u;
    R2(17) R2(29) R2(16) R2(24)
    a0 += TF_K1; a1 += TF_K2 + 4u;  b0 += TF_K1; b1 += TF_K2 + 4u;
    R2(13) R2(15) R2(26) R2(6)
    a0 += TF_K2; a1 += TF_K0 + 5u;  b0 += TF_K2; b1 += TF_K0 + 5u;
#undef R2
    oA = a0 ^ a1; oB = b0 ^ b1;
}

// ---------------------------------------------------------------------------
// Prep: fp16 convert of scaled Q concat and K concat; bf16 hi/lo of V=v1+v2.
// ---------------------------------------------------------------------------
__device__ __forceinline__ uint32_t h2pack(float lo, float hi) {
    uint32_t r;
    asm("cvt.rn.f16x2.f32 %0, %1, %2;" : "=r"(r) : "f"(hi), "f"(lo));
    return r;
}

__device__ __forceinline__ void split4bf(float4 v, uint2& hi, uint2& lo) {
    __nv_bfloat16 h0 = __float2bfloat16_rn(v.x);
    __nv_bfloat16 h1 = __float2bfloat16_rn(v.y);
    __nv_bfloat16 h2 = __float2bfloat16_rn(v.z);
    __nv_bfloat16 h3 = __float2bfloat16_rn(v.w);
    __nv_bfloat16 l0 = __float2bfloat16_rn(v.x - __bfloat162float(h0));
    __nv_bfloat16 l1 = __float2bfloat16_rn(v.y - __bfloat162float(h1));
    __nv_bfloat16 l2 = __float2bfloat16_rn(v.z - __bfloat162float(h2));
    __nv_bfloat16 l3 = __float2bfloat16_rn(v.w - __bfloat162float(h3));
    hi.x = (uint32_t)*(uint16_t*)&h0 | ((uint32_t)*(uint16_t*)&h1 << 16);
    hi.y = (uint32_t)*(uint16_t*)&h2 | ((uint32_t)*(uint16_t*)&h3 << 16);
    lo.x = (uint32_t)*(uint16_t*)&l0 | ((uint32_t)*(uint16_t*)&l1 << 16);
    lo.y = (uint32_t)*(uint16_t*)&l2 | ((uint32_t)*(uint16_t*)&l3 << 16);
}

__global__ void __launch_bounds__(256) prep_kernel(
    const float* __restrict__ q1, const float* __restrict__ q2,
    const float* __restrict__ k1, const float* __restrict__ k2,
    const float* __restrict__ v1, const float* __restrict__ v2)
{
    const int idx4 = blockIdx.x * 256 + threadIdx.x;
    const int row  = idx4 >> 4;
    const int d4   = idx4 & 15;
    const float4 a1 = ((const float4*)q1)[idx4];
    const float4 a2 = ((const float4*)q2)[idx4];
    const float4 b1 = ((const float4*)k1)[idx4];
    const float4 b2 = ((const float4*)k2)[idx4];
    const float4 c1 = ((const float4*)v1)[idx4];
    const float4 c2 = ((const float4*)v2)[idx4];
    const float s = 0.125f;
    const int qb = row * 128 + d4 * 4;
    uint2 pa, pb;
    pa.x = h2pack(a1.x * s, a1.y * s); pa.y = h2pack(a1.z * s, a1.w * s);
    pb.x = h2pack(a2.x * s, a2.y * s); pb.y = h2pack(a2.z * s, a2.w * s);
    *(uint2*)(gQ + qb) = pa; *(uint2*)(gQ + qb + 64) = pb;
    pa.x = h2pack(b1.x, b1.y); pa.y = h2pack(b1.z, b1.w);
    pb.x = h2pack(b2.x, b2.y); pb.y = h2pack(b2.z, b2.w);
    *(uint2*)(gK + qb) = pa; *(uint2*)(gK + qb + 64) = pb;
    float4 vs = make_float4(c1.x+c2.x, c1.y+c2.y, c1.z+c2.z, c1.w+c2.w);
    uint2 hi, lo;
    split4bf(vs, hi, lo);
    *(uint2*)(gVh + row * 64 + d4 * 4) = hi;
    *(uint2*)(gVl + row * 64 + d4 * 4) = lo;
}

// ---------------------------------------------------------------------------
// mma / ldmatrix / cp.async helpers
// ---------------------------------------------------------------------------
__device__ __forceinline__ void ldsm_x4(uint32_t& r0, uint32_t& r1,
                                        uint32_t& r2, uint32_t& r3, uint32_t addr) {
    asm volatile("ldmatrix.sync.aligned.m8n8.x4.shared.b16 {%0,%1,%2,%3}, [%4];"
                 : "=r"(r0), "=r"(r1), "=r"(r2), "=r"(r3) : "r"(addr));
}
__device__ __forceinline__ void ldsm_x4_t(uint32_t& r0, uint32_t& r1,
                                          uint32_t& r2, uint32_t& r3, uint32_t addr) {
    asm volatile("ldmatrix.sync.aligned.m8n8.x4.trans.shared.b16 {%0,%1,%2,%3}, [%4];"
                 : "=r"(r0), "=r"(r1), "=r"(r2), "=r"(r3) : "r"(addr));
}
__device__ __forceinline__ void mma_f16(float* c, const uint32_t* a,
                                        uint32_t b0, uint32_t b1) {
    asm volatile("mma.sync.aligned.m16n8k16.row.col.f32.f16.f16.f32 "
                 "{%0,%1,%2,%3}, {%4,%5,%6,%7}, {%8,%9}, {%0,%1,%2,%3};"
                 : "+f"(c[0]), "+f"(c[1]), "+f"(c[2]), "+f"(c[3])
                 : "r"(a[0]), "r"(a[1]), "r"(a[2]), "r"(a[3]), "r"(b0), "r"(b1));
}
__device__ __forceinline__ void mma_bf16(float* c, const uint32_t* a,
                                         uint32_t b0, uint32_t b1) {
    asm volatile("mma.sync.aligned.m16n8k16.row.col.f32.bf16.bf16.f32 "
                 "{%0,%1,%2,%3}, {%4,%5,%6,%7}, {%8,%9}, {%0,%1,%2,%3};"
                 : "+f"(c[0]), "+f"(c[1]), "+f"(c[2]), "+f"(c[3])
                 : "r"(a[0]), "r"(a[1]), "r"(a[2]), "r"(a[3]), "r"(b0), "r"(b1));
}
__device__ __forceinline__ void cpa16(uint32_t s, const void* g) {
    asm volatile("cp.async.cg.shared.global [%0], [%1], 16;" :: "r"(s), "l"(g));
}
#define CP_COMMIT() asm volatile("cp.async.commit_group;" ::: "memory")
#define CP_WAIT0()  asm volatile("cp.async.wait_group 0;" ::: "memory")

// pack two fp32 into bf16x2 (low = x0) and compute the bf16x2 residual
__device__ __forceinline__ void split_pack(float x0, float x1,
                                           uint32_t& hi, uint32_t& lo) {
    uint32_t h;
    asm("cvt.rn.bf16x2.f32 %0, %1, %2;" : "=r"(h) : "f"(x1), "f"(x0));
    float h0 = __uint_as_float(h << 16);
    float h1 = __uint_as_float(h & 0xffff0000u);
    float r0 = x0 - h0, r1 = x1 - h1;
    uint32_t l;
    asm("cvt.rn.bf16x2.f32 %0, %1, %2;" : "=r"(l) : "f"(r1), "f"(r0));
    hi = h; lo = l;
}

// smem swizzles (b16 element offsets). 128-wide rows (Q/K), 64-wide (V).
__device__ __forceinline__ int swb(int r, int ch) { return r * 128 + ((ch ^ (r & 7)) << 3); }
__device__ __forceinline__ int swv(int r, int ch) { return r * 64  + ((ch ^ (r & 7)) << 3); }

// ---------------------------------------------------------------------------
// Fused FA2 attention: QK = single fp16 MMA, PV = bf16 3-split MMA.
// Threefry mask generation interleaved INSIDE the QK MMA loop (intra-warp
// ALU/tensor overlap). Pair-local named barriers for max/sum/mask exchange.
// BR=BC=64, 256 threads. Warp (w_r, w_c): 16-row block, 32-col t-slice.
// ---------------------------------------------------------------------------
__global__ void __launch_bounds__(256, 2) attn_kernel(float* __restrict__ out)
{
    extern __shared__ char smem[];
    __half*        sQ  = (__half*)smem;                     // 16 KB
    __half*        sK  = (__half*)(smem + 16384);           // 16 KB
    __nv_bfloat16* sVh = (__nv_bfloat16*)(smem + 32768);    // 8 KB
    __nv_bfloat16* sVl = (__nv_bfloat16*)(smem + 40960);    // 8 KB
    float*    sMax  = (float*)(smem + 49152);               // [2][64]
    float*    sSum  = (float*)(smem + 49664);               // [2][64]
    uint32_t* sMask = (uint32_t*)(smem + 50176);            // [64][2]

    const int tid = threadIdx.x;
    const int lane = tid & 31;
    const int w    = tid >> 5;
    const int w_r  = w & 3;
    const int w_c  = w >> 2;
    const int bh  = blockIdx.y;
    const int s0  = blockIdx.x << 6;
    const size_t rowbase128 = (size_t)bh * SS * 128;
    const size_t rowbase64  = (size_t)bh * SS * 64;

    const uint32_t sQ_a  = (uint32_t)__cvta_generic_to_shared(sQ);
    const uint32_t sK_a  = (uint32_t)__cvta_generic_to_shared(sK);
    const uint32_t sVh_a = (uint32_t)__cvta_generic_to_shared(sVh);
    const uint32_t sVl_a = (uint32_t)__cvta_generic_to_shared(sVl);

    // ---- Q tile cp.async (waits folded into first iteration's load wait) ----
    {
        const __half* gq = gQ + rowbase128 + (size_t)s0 * 128;
        for (int it = tid; it < 1024; it += 256) {
            int r = it >> 4, ch = it & 15;
            cpa16(sQ_a + (uint32_t)(swb(r, ch) * 2), gq + r * 128 + ch * 8);
        }
    }

    const int arow  = 16 * w_r + (lane & 15);
    const int g     = lane >> 3;
    const int brow0 = 32 * w_c + 8 * (g >> 1) + (lane & 7);
    const int brow1 = brow0 + 16;
    const int bpar  = g & 1;

    const int row0 = 16 * w_r + (lane >> 2);
    const int row1 = row0 + 8;
    // mask element base for this warp's generated rows (r = 16*w_r + 8*w_c + kb)
    const uint32_t ibase = ((uint32_t)bh << 22)
                         + (((uint32_t)(s0 + 16 * w_r + 8 * w_c)) << 11) + (uint32_t)lane;

    float m00 = -3.0e38f, m01 = -3.0e38f, l00 = 0.0f, l01 = 0.0f;
    float o[8][4];
#pragma unroll
    for (int nb = 0; nb < 8; nb++)
#pragma unroll
        for (int i = 0; i < 4; i++) o[nb][i] = 0.0f;

    for (int t0 = 0; t0 < SS; t0 += 64) {
        // ---- K and V tiles via cp.async ----
        {
            const __half* gk = gK + rowbase128 + (size_t)t0 * 128;
            for (int it = tid; it < 1024; it += 256) {
                int r = it >> 4, ch = it & 15;
                cpa16(sK_a + (uint32_t)(swb(r, ch) * 2), gk + r * 128 + ch * 8);
            }
            const __nv_bfloat16* gvh = gVh + rowbase64 + (size_t)t0 * 64;
            const __nv_bfloat16* gvl = gVl + rowbase64 + (size_t)t0 * 64;
            for (int it = tid; it < 512; it += 256) {
                int r = it >> 3, ch = it & 7;
                uint32_t off = (uint32_t)(swv(r, ch) * 2);
                cpa16(sVh_a + off, gvh + r * 64 + ch * 8);
                cpa16(sVl_a + off, gvl + r * 64 + ch * 8);
            }
        }
        CP_COMMIT();
        CP_WAIT0();
        __syncthreads();

        // ---- fused QK (fp16 single MMA) + threefry mask gen, interleaved ----
        float cfr[4][4];
#pragma unroll
        for (int nb = 0; nb < 4; nb++)
#pragma unroll
            for (int i = 0; i < 4; i++) cfr[nb][i] = 0.0f;

        const uint32_t ib = ibase + (uint32_t)t0;
#pragma unroll 2
        for (int kb = 0; kb < 8; kb++) {
            // dual threefry (ALU pipe) — independent of the MMA stream below,
            // ptxas interleaves it into ldsm/HMMA latency.
            uint32_t iA = ib + ((uint32_t)kb << 11);
            uint32_t oA, oB;
            threefry_dual(iA, iA + 32u, oA, oB);
            uint32_t wA = __ballot_sync(0xffffffffu, (int)oA >= 0);
            uint32_t wB = __ballot_sync(0xffffffffu, (int)oB >= 0);
            if (lane == 0) {
                const int mr = 16 * w_r + 8 * w_c + kb;
                sMask[2 * mr]     = wA;
                sMask[2 * mr + 1] = wB;
            }

            const int ach = 2 * kb + (lane >> 4);
            uint32_t q[4];
            ldsm_x4(q[0], q[1], q[2], q[3], sQ_a + (uint32_t)(swb(arow, ach) * 2));
            const int bch = 2 * kb + bpar;
            uint32_t k0[4], k1[4];
            ldsm_x4(k0[0], k0[1], k0[2], k0[3], sK_a + (uint32_t)(swb(brow0, bch) * 2));
            ldsm_x4(k1[0], k1[1], k1[2], k1[3], sK_a + (uint32_t)(swb(brow1, bch) * 2));
            mma_f16(cfr[0], q, k0[0], k0[1]);
            mma_f16(cfr[1], q, k0[2], k0[3]);
            mma_f16(cfr[2], q, k1[0], k1[1]);
            mma_f16(cfr[3], q, k1[2], k1[3]);
        }

        // ---- fragment-domain online softmax (pair-local exchange) ----
        float mx0 = fmaxf(fmaxf(cfr[0][0], cfr[0][1]), fmaxf(cfr[1][0], cfr[1][1]));
        mx0 = fmaxf(mx0, fmaxf(fmaxf(cfr[2][0], cfr[2][1]), fmaxf(cfr[3][0], cfr[3][1])));
        float mx1 = fmaxf(fmaxf(cfr[0][2], cfr[0][3]), fmaxf(cfr[1][2], cfr[1][3]));
        mx1 = fmaxf(mx1, fmaxf(fmaxf(cfr[2][2], cfr[2][3]), fmaxf(cfr[3][2], cfr[3][3])));
        mx0 = fmaxf(mx0, __shfl_xor_sync(0xffffffffu, mx0, 1));
        mx0 = fmaxf(mx0, __shfl_xor_sync(0xffffffffu, mx0, 2));
        mx1 = fmaxf(mx1, __shfl_xor_sync(0xffffffffu, mx1, 1));
        mx1 = fmaxf(mx1, __shfl_xor_sync(0xffffffffu, mx1, 2));
        if ((lane & 3) == 0) {
            sMax[w_c * 64 + row0] = mx0;
            sMax[w_c * 64 + row1] = mx1;
        }
        // pair barrier: warps (w_r,0) and (w_r,1) only (covers sMask too)
        asm volatile("bar.sync %0, %1;" :: "r"(1 + w_r), "r"(64) : "memory");

        const float newm0 = fmaxf(m00, fmaxf(sMax[row0], sMax[64 + row0]));
        const float newm1 = fmaxf(m01, fmaxf(sMax[row1], sMax[64 + row1]));
        const float f0 = __expf(m00 - newm0);
        const float f1 = __expf(m01 - newm1);

        const uint32_t wm0 = sMask[2 * row0 + w_c];
        const uint32_t wm1 = sMask[2 * row1 + w_c];

        float rs0 = 0.0f, rs1 = 0.0f;
        const int bsh = 2 * (lane & 3);
#pragma unroll
        for (int nb = 0; nb < 4; nb++) {
            const int sh = 8 * nb + bsh;
            float p0 = __expf(cfr[nb][0] - newm0); rs0 += p0;
            float p1 = __expf(cfr[nb][1] - newm0); rs0 += p1;
            float p2 = __expf(cfr[nb][2] - newm1); rs1 += p2;
            float p3 = __expf(cfr[nb][3] - newm1); rs1 += p3;
            cfr[nb][0] = ((wm0 >> sh)       & 1u) ? p0 : 0.0f;
            cfr[nb][1] = ((wm0 >> (sh + 1)) & 1u) ? p1 : 0.0f;
            cfr[nb][2] = ((wm1 >> sh)       & 1u) ? p2 : 0.0f;
            cfr[nb][3] = ((wm1 >> (sh + 1)) & 1u) ? p3 : 0.0f;
        }
        rs0 += __shfl_xor_sync(0xffffffffu, rs0, 1);
        rs0 += __shfl_xor_sync(0xffffffffu, rs0, 2);
        rs1 += __shfl_xor_sync(0xffffffffu, rs1, 1);
        rs1 += __shfl_xor_sync(0xffffffffu, rs1, 2);
        if ((lane & 3) == 0) {
            sSum[w_c * 64 + row0] = rs0;
            sSum[w_c * 64 + row1] = rs1;
        }

        // rescale partial O fragments
#pragma unroll
        for (int nb = 0; nb < 8; nb++) {
            o[nb][0] *= f0; o[nb][1] *= f0;
            o[nb][2] *= f1; o[nb][3] *= f1;
        }

        // ---- PV: P (registers, bf16 3-split) x V (ldmatrix.trans) ----
#pragma unroll
        for (int kb2 = 0; kb2 < 2; kb2++) {
            uint32_t ah[4], al[4];
            split_pack(cfr[2*kb2][0],   cfr[2*kb2][1],   ah[0], al[0]);
            split_pack(cfr[2*kb2][2],   cfr[2*kb2][3],   ah[1], al[1]);
            split_pack(cfr[2*kb2+1][0], cfr[2*kb2+1][1], ah[2], al[2]);
            split_pack(cfr[2*kb2+1][2], cfr[2*kb2+1][3], ah[3], al[3]);
            const int vkrow = 32 * w_c + 16 * kb2 + (lane & 15);
#pragma unroll
            for (int nb16 = 0; nb16 < 4; nb16++) {
                const int ch = 2 * nb16 + (lane >> 4);
                const uint32_t voff = (uint32_t)(swv(vkrow, ch) * 2);
                uint32_t vh[4], vl[4];
                ldsm_x4_t(vh[0], vh[1], vh[2], vh[3], sVh_a + voff);
                ldsm_x4_t(vl[0], vl[1], vl[2], vl[3], sVl_a + voff);
                mma_bf16(o[2*nb16],   ah, vh[0], vh[1]);
                mma_bf16(o[2*nb16],   ah, vl[0], vl[1]);
                mma_bf16(o[2*nb16],   al, vh[0], vh[1]);
                mma_bf16(o[2*nb16+1], ah, vh[2], vh[3]);
                mma_bf16(o[2*nb16+1], ah, vl[2], vl[3]);
                mma_bf16(o[2*nb16+1], al, vh[2], vh[3]);
            }
        }
        __syncthreads();

        l00 = l00 * f0 + sSum[row0] + sSum[64 + row0];
        l01 = l01 * f1 + sSum[row1] + sSum[64 + row1];
        m00 = newm0; m01 = newm1;
    }

    // ---- epilogue: sum partner-warp partials, scale by 2/l, store ----
    float* sO = (float*)smem;   // reuse Q area (all Q reads complete)
    if (w_c == 1) {
#pragma unroll
        for (int nb = 0; nb < 8; nb++) {
            const int col = 8 * nb + 2 * (lane & 3);
            *(float2*)(sO + row0 * 64 + col) = make_float2(o[nb][0], o[nb][1]);
            *(float2*)(sO + row1 * 64 + col) = make_float2(o[nb][2], o[nb][3]);
        }
    }
    __syncthreads();
    if (w_c == 0) {
        const float inv0 = 2.0f / l00;
        const float inv1 = 2.0f / l01;
        float* obase = out + (size_t)bh * SS * DD;
#pragma unroll
        for (int nb = 0; nb < 8; nb++) {
            const int col = 8 * nb + 2 * (lane & 3);
            float2 q0 = *(float2*)(sO + row0 * 64 + col);
            float2 q1 = *(float2*)(sO + row1 * 64 + col);
            float2 r0 = make_float2((o[nb][0] + q0.x) * inv0, (o[nb][1] + q0.y) * inv0);
            float2 r1 = make_float2((o[nb][2] + q1.x) * inv1, (o[nb][3] + q1.y) * inv1);
            *(float2*)(obase + (size_t)(s0 + row0) * DD + col) = r0;
            *(float2*)(obase + (size_t)(s0 + row1) * DD + col) = r1;
        }
    }
}

// ---------------------------------------------------------------------------
extern "C" void kernel_launch(void* const* d_in, const int* in_sizes, int n_in,
                              void* d_out, int out_size) {
    (void)in_sizes; (void)n_in; (void)out_size;
    const float* q1 = (const float*)d_in[0];
    const float* q2 = (const float*)d_in[1];
    const float* k1 = (const float*)d_in[2];
    const float* k2 = (const float*)d_in[3];
    const float* v1 = (const float*)d_in[4];
    const float* v2 = (const float*)d_in[5];
    float* out = (float*)d_out;

    prep_kernel<<<(NBH * SS * DD / 4) / 256, 256>>>(q1, q2, k1, k2, v1, v2);

    const int smem_bytes = 50688;
    cudaFuncSetAttribute(attn_kernel,
                         cudaFuncAttributeMaxDynamicSharedMemorySize, smem_bytes);
    attn_kernel<<<dim3(SS / 64, NBH), 256, smem_bytes>>>(out);
}